// round 13
// baseline (speedup 1.0000x reference)
#include <cuda_runtime.h>
#include <cuda_bf16.h>
#include <math.h>
#include <stdint.h>

// Problem shape (fixed by the reference)
constexpr int BB = 4;
constexpr int TT = 2048;
constexpr int CC = 1024;
constexpr int HH = 16;
constexpr int DD = 64;
constexpr int MTOT = BB * TT;     // 8192
constexpr int NQKV = 3 * CC;      // 3072
constexpr int KDIM = CC;          // 1024

// ---------------------------------------------------------------------------
// Scratch (device globals — no allocation allowed)
// ---------------------------------------------------------------------------
__device__ __align__(16) float g_q[(size_t)BB * HH * TT * DD];   // [B,H,T,D] fp32
__device__ __align__(16) float g_k[(size_t)BB * HH * TT * DD];

// bf16 split-precision copies (hi + lo)
__device__ __align__(16) __nv_bfloat16 g_x_hi[(size_t)MTOT * CC];
__device__ __align__(16) __nv_bfloat16 g_x_lo[(size_t)MTOT * CC];
__device__ __align__(16) __nv_bfloat16 g_w_hi[(size_t)NQKV * CC];
__device__ __align__(16) __nv_bfloat16 g_w_lo[(size_t)NQKV * CC];
__device__ __align__(16) __nv_bfloat16 g_pw_hi[(size_t)CC * CC];
__device__ __align__(16) __nv_bfloat16 g_pw_lo[(size_t)CC * CC];
__device__ __align__(16) __nv_bfloat16 g_y_hi[(size_t)MTOT * CC];
__device__ __align__(16) __nv_bfloat16 g_y_lo[(size_t)MTOT * CC];

// attention operands in bf16 hi/lo, [B,H,T,D]
__device__ __align__(16) __nv_bfloat16 g_qhi[(size_t)BB * HH * TT * DD];
__device__ __align__(16) __nv_bfloat16 g_qlo[(size_t)BB * HH * TT * DD];
__device__ __align__(16) __nv_bfloat16 g_khi[(size_t)BB * HH * TT * DD];
__device__ __align__(16) __nv_bfloat16 g_klo[(size_t)BB * HH * TT * DD];
__device__ __align__(16) __nv_bfloat16 g_vhi[(size_t)BB * HH * TT * DD];
__device__ __align__(16) __nv_bfloat16 g_vlo[(size_t)BB * HH * TT * DD];

// ---------------------------------------------------------------------------
// PTX helpers (compute_103-safe: mma.sync / ldmatrix / cp.async only)
// ---------------------------------------------------------------------------
__device__ __forceinline__ uint32_t smem_u32(const void* p) {
    uint32_t a;
    asm("{ .reg .u64 t; cvta.to.shared.u64 t, %1; cvt.u32.u64 %0, t; }"
        : "=r"(a) : "l"(p));
    return a;
}
__device__ __forceinline__ void cp16(uint32_t dst, const void* src) {
    asm volatile("cp.async.cg.shared.global [%0], [%1], 16;"
                 :: "r"(dst), "l"(src) : "memory");
}
__device__ __forceinline__ void cp_commit() {
    asm volatile("cp.async.commit_group;" ::: "memory");
}
template <int N>
__device__ __forceinline__ void cp_wait() {
    asm volatile("cp.async.wait_group %0;" :: "n"(N) : "memory");
}
__device__ __forceinline__ void ldsm_x4(uint32_t* r, uint32_t addr) {
    asm volatile("ldmatrix.sync.aligned.m8n8.x4.shared.b16 {%0,%1,%2,%3}, [%4];"
                 : "=r"(r[0]), "=r"(r[1]), "=r"(r[2]), "=r"(r[3]) : "r"(addr));
}
__device__ __forceinline__ void ldsm_x4_t(uint32_t* r, uint32_t addr) {
    asm volatile("ldmatrix.sync.aligned.m8n8.x4.trans.shared.b16 {%0,%1,%2,%3}, [%4];"
                 : "=r"(r[0]), "=r"(r[1]), "=r"(r[2]), "=r"(r[3]) : "r"(addr));
}
__device__ __forceinline__ void mma16816(float* c, const uint32_t* a,
                                         const uint32_t* b) {
    asm volatile(
        "mma.sync.aligned.m16n8k16.row.col.f32.bf16.bf16.f32 "
        "{%0,%1,%2,%3}, {%4,%5,%6,%7}, {%8,%9}, {%0,%1,%2,%3};"
        : "+f"(c[0]), "+f"(c[1]), "+f"(c[2]), "+f"(c[3])
        : "r"(a[0]), "r"(a[1]), "r"(a[2]), "r"(a[3]), "r"(b[0]), "r"(b[1]));
}
// Split a float pair into packed bf16 hi and bf16 lo (low half = first elem)
__device__ __forceinline__ void pack2(float a, float b, uint32_t& hi, uint32_t& lo) {
    __nv_bfloat162 h = __floats2bfloat162_rn(a, b);
    __nv_bfloat162 l = __floats2bfloat162_rn(a - __bfloat162float(h.x),
                                             b - __bfloat162float(h.y));
    hi = *(uint32_t*)&h;
    lo = *(uint32_t*)&l;
}

// ---------------------------------------------------------------------------
// Split fp32 -> bf16 hi + bf16 lo.  W selects the (dst hi, dst lo) pair.
// ---------------------------------------------------------------------------
template <int W>
__global__ __launch_bounds__(256) void split_k(const float* __restrict__ s)
{
    __nv_bfloat16 *hi, *lo;
    if (W == 0)      { hi = g_x_hi;  lo = g_x_lo;  }
    else if (W == 1) { hi = g_w_hi;  lo = g_w_lo;  }
    else             { hi = g_pw_hi; lo = g_pw_lo; }

    const size_t base = ((size_t)blockIdx.x * 256 + threadIdx.x) * 8;
    float4 v0 = *(const float4*)(s + base);
    float4 v1 = *(const float4*)(s + base + 4);
    float v[8] = {v0.x, v0.y, v0.z, v0.w, v1.x, v1.y, v1.z, v1.w};
    __align__(16) __nv_bfloat16 h[8];
    __align__(16) __nv_bfloat16 l[8];
#pragma unroll
    for (int i = 0; i < 8; i++) {
        h[i] = __float2bfloat16_rn(v[i]);
        l[i] = __float2bfloat16_rn(v[i] - __bfloat162float(h[i]));
    }
    *(uint4*)(hi + base) = *(const uint4*)h;
    *(uint4*)(lo + base) = *(const uint4*)l;
}

// Split q (scaled by 1/8) or k into bf16 hi/lo after rope.
template <int IS_Q>
__global__ __launch_bounds__(256) void qk_split()
{
    const float* s = IS_Q ? g_q : g_k;
    __nv_bfloat16* hi = IS_Q ? g_qhi : g_khi;
    __nv_bfloat16* lo = IS_Q ? g_qlo : g_klo;
    const float scale = IS_Q ? 0.125f : 1.0f;
    const size_t base = ((size_t)blockIdx.x * 256 + threadIdx.x) * 8;
    float4 v0 = *(const float4*)(s + base);
    float4 v1 = *(const float4*)(s + base + 4);
    float v[8] = {v0.x, v0.y, v0.z, v0.w, v1.x, v1.y, v1.z, v1.w};
    __align__(16) __nv_bfloat16 h[8];
    __align__(16) __nv_bfloat16 l[8];
#pragma unroll
    for (int i = 0; i < 8; i++) {
        const float f = v[i] * scale;
        h[i] = __float2bfloat16_rn(f);
        l[i] = __float2bfloat16_rn(f - __bfloat162float(h[i]));
    }
    *(uint4*)(hi + base) = *(const uint4*)h;
    *(uint4*)(lo + base) = *(const uint4*)l;
}

// ---------------------------------------------------------------------------
// HMMA bf16x3 GEMM: C[M,N] = A[M,K] * B[N,K]^T in split precision.
// BM=BN=128, BK=32. 8 warps (2x4), each 64x32. Double-buffered cp.async.
// MODE 0: q,k fp32 scatter; v written directly as bf16 hi/lo.
// MODE 1: +bias -> out.
// ---------------------------------------------------------------------------
constexpr int BK = 32;
constexpr int NC = KDIM / BK;              // 32 k-chunks
constexpr int RS = 80;                     // smem row stride (bytes)
constexpr int TILE_B = 128 * RS;           // 10240 B per tile
constexpr int BUF_B = 4 * TILE_B;          // Ah, Al, Bh, Bl = 40960 B
constexpr int GEMM_SMEM = 2 * BUF_B;       // 81920 B

template <int MODE>
__global__ __launch_bounds__(256, 1)
void gemm_tc(const float* __restrict__ bias, float* __restrict__ out, int N)
{
    extern __shared__ char sp[];
    const uint32_t sb = smem_u32(sp);

    const int tid  = threadIdx.x;
    const int wid  = tid >> 5;
    const int lane = tid & 31;
    const int wm   = wid >> 2;
    const int wn   = wid & 3;
    const int tileM = blockIdx.y * 128;
    const int tileN = blockIdx.x * 128;

    const __nv_bfloat16* Ah = (MODE == 0) ? g_x_hi : g_y_hi;
    const __nv_bfloat16* Al = (MODE == 0) ? g_x_lo : g_y_lo;
    const __nv_bfloat16* Bh = (MODE == 0) ? g_w_hi : g_pw_hi;
    const __nv_bfloat16* Bl = (MODE == 0) ? g_w_lo : g_pw_lo;

    const int lrow = tid >> 1;
    const int lcb  = (tid & 1) * 2;
    const size_t gA = (size_t)(tileM + lrow) * KDIM + lcb * 8;
    const size_t gB = (size_t)(tileN + lrow) * KDIM + lcb * 8;
    const uint32_t sOff = (uint32_t)(lrow * RS + lcb * 16);

    auto prefetch = [&](int c) {
        const uint32_t bb = sb + (c & 1) * BUF_B;
        const int k0 = c * BK;
        cp16(bb + sOff,                Ah + gA + k0);
        cp16(bb + sOff + 16,           Ah + gA + k0 + 8);
        cp16(bb + TILE_B + sOff,       Al + gA + k0);
        cp16(bb + TILE_B + sOff + 16,  Al + gA + k0 + 8);
        cp16(bb + 2 * TILE_B + sOff,      Bh + gB + k0);
        cp16(bb + 2 * TILE_B + sOff + 16, Bh + gB + k0 + 8);
        cp16(bb + 3 * TILE_B + sOff,      Bl + gB + k0);
        cp16(bb + 3 * TILE_B + sOff + 16, Bl + gB + k0 + 8);
        cp_commit();
    };

    const uint32_t aoff = (uint32_t)((wm * 64 + (lane & 15)) * RS +
                                     ((lane >> 4) * 16));
    const uint32_t boff = (uint32_t)((wn * 32 + ((lane >> 4) << 3) + (lane & 7)) * RS +
                                     (((lane >> 3) & 1) * 16));

    float acc[4][4][4];
#pragma unroll
    for (int i = 0; i < 4; i++)
#pragma unroll
        for (int j = 0; j < 4; j++)
#pragma unroll
            for (int e = 0; e < 4; e++) acc[i][j][e] = 0.0f;

    prefetch(0);

    for (int c = 0; c < NC; ++c) {
        if (c + 1 < NC) prefetch(c + 1);
        if (c + 1 < NC) cp_wait<1>(); else cp_wait<0>();
        __syncthreads();

        const uint32_t bb = sb + (c & 1) * BUF_B;
#pragma unroll
        for (int ks = 0; ks < 2; ++ks) {
            const uint32_t kb = ks * 32;
            uint32_t ah[4][4], al[4][4], bh[2][4], bl[2][4];
#pragma unroll
            for (int mi = 0; mi < 4; ++mi) {
                ldsm_x4(ah[mi], bb + aoff + mi * (16 * RS) + kb);
                ldsm_x4(al[mi], bb + TILE_B + aoff + mi * (16 * RS) + kb);
            }
#pragma unroll
            for (int n2 = 0; n2 < 2; ++n2) {
                ldsm_x4(bh[n2], bb + 2 * TILE_B + boff + n2 * (16 * RS) + kb);
                ldsm_x4(bl[n2], bb + 3 * TILE_B + boff + n2 * (16 * RS) + kb);
            }
#pragma unroll
            for (int mi = 0; mi < 4; ++mi)
#pragma unroll
                for (int ni = 0; ni < 4; ++ni) {
                    const uint32_t* bhp = &bh[ni >> 1][(ni & 1) * 2];
                    const uint32_t* blp = &bl[ni >> 1][(ni & 1) * 2];
                    mma16816(acc[mi][ni], ah[mi], bhp);
                    mma16816(acc[mi][ni], ah[mi], blp);
                    mma16816(acc[mi][ni], al[mi], bhp);
                }
        }
        __syncthreads();
    }

    const int g4 = lane >> 2;
    const int t4 = lane & 3;
#pragma unroll
    for (int mi = 0; mi < 4; ++mi) {
        const int m0 = tileM + wm * 64 + mi * 16 + g4;
#pragma unroll
        for (int ni = 0; ni < 4; ++ni) {
            const int n = tileN + wn * 32 + ni * 8 + t4 * 2;
            float2 v0 = make_float2(acc[mi][ni][0], acc[mi][ni][1]);
            float2 v1 = make_float2(acc[mi][ni][2], acc[mi][ni][3]);
            if (MODE == 0) {
                const int which = n >> 10;
                const int h = (n & 1023) >> 6;
                const int d = n & 63;
                const int m1 = m0 + 8;
                const size_t i0 =
                    (((size_t)((m0 >> 11) * HH + h)) * TT + (m0 & 2047)) * DD + d;
                const size_t i1 =
                    (((size_t)((m1 >> 11) * HH + h)) * TT + (m1 & 2047)) * DD + d;
                if (which == 2) {
                    uint32_t hh, ll;
                    pack2(v0.x, v0.y, hh, ll);
                    *(uint32_t*)(g_vhi + i0) = hh;
                    *(uint32_t*)(g_vlo + i0) = ll;
                    pack2(v1.x, v1.y, hh, ll);
                    *(uint32_t*)(g_vhi + i1) = hh;
                    *(uint32_t*)(g_vlo + i1) = ll;
                } else {
                    float* dst = (which == 0) ? g_q : g_k;
                    *(float2*)&dst[i0] = v0;
                    *(float2*)&dst[i1] = v1;
                }
            } else {
                const float2 bv = *(const float2*)&bias[n];
                v0.x += bv.x; v0.y += bv.y;
                v1.x += bv.x; v1.y += bv.y;
                *(float2*)&out[(size_t)m0 * N + n] = v0;
                *(float2*)&out[(size_t)(m0 + 8) * N + n] = v1;
            }
        }
    }
}

// ---------------------------------------------------------------------------
// RoPE in-place on g_q and g_k (only 16 nonzero-frequency pairs per head).
// ---------------------------------------------------------------------------
__global__ void rope_kernel()
{
    const int idx = blockIdx.x * blockDim.x + threadIdx.x;
    const int p = idx & 15;
    const int t = (idx >> 4) & (TT - 1);
    const int bh = idx >> 15;

    const float af = (float)pow(1.0 / 1024.0, (double)p / 15.0);
    const float theta = (float)t * af;
    double sd, cd;
    sincos((double)theta, &sd, &cd);
    const float c = (float)cd, s = (float)sd;

    const size_t base = ((size_t)bh * TT + t) * DD;
    const float q1 = g_q[base + p], q2 = g_q[base + p + 32];
    g_q[base + p]      = q1 * c + q2 * s;
    g_q[base + p + 32] = -q1 * s + q2 * c;
    const float k1 = g_k[base + p], k2 = g_k[base + p + 32];
    g_k[base + p]      = k1 * c + k2 * s;
    g_k[base + p + 32] = -k1 * s + k2 * c;
}

// ---------------------------------------------------------------------------
// Flash attention on HMMA, causal. Br=128 (8 warps x m16), Bc=64.
// Q fragments in registers; K/V hi/lo double-buffered via cp.async.
// S = Qhi Khi + Qhi Klo + Qlo Khi; P split in registers; O += Phi Vhi + ...
// Writes y directly as bf16 hi/lo for the projection GEMM.
// ---------------------------------------------------------------------------
constexpr int RSF = 144;                    // 128B data + 16B pad
constexpr int KVT = 64 * RSF;               // 9216 B per 64x64 bf16 tile
constexpr int KVBUF = 4 * KVT;              // Khi,Klo,Vhi,Vlo = 36864 B
constexpr int FSMEM = 2 * KVBUF;            // 73728 B

__global__ __launch_bounds__(256, 1)
void flash_tc()
{
    extern __shared__ char sp[];
    const uint32_t sb = smem_u32(sp);
    const int qt = 15 - blockIdx.x;         // heavy tiles first
    const int bh = blockIdx.y;
    const int tid = threadIdx.x;
    const int w = tid >> 5;
    const int lane = tid & 31;
    const int g = lane >> 2;
    const int tq = lane & 3;
    const int ntiles = 2 * qt + 2;

    // Stage Q hi/lo into buffer-1 region (reused for kv tile 1 later)
    {
        const size_t qb = ((size_t)bh * TT + (size_t)qt * 128) * DD;
#pragma unroll
        for (int t = 0; t < 8; ++t) {
            const int half = t >> 2;                  // 0: hi, 1: lo
            const int within = (t & 3) * 256 + tid;   // 0..1023
            const int row = within >> 3, c8 = within & 7;
            const __nv_bfloat16* src =
                (half ? g_qlo : g_qhi) + qb + row * 64 + c8 * 8;
            cp16(sb + KVBUF + half * (128 * RSF) + row * RSF + c8 * 16, src);
        }
        cp_commit();
    }

    auto prefetch_kv = [&](int j) {
        const uint32_t dstb = sb + (j & 1) * KVBUF;
        const size_t rb = (size_t)bh * TT + (size_t)j * 64;
#pragma unroll
        for (int t = 0; t < 8; ++t) {
            const int tile = t >> 1;                  // 0..3
            const int within = (t & 1) * 256 + tid;   // 0..511
            const int row = within >> 3, c8 = within & 7;
            const __nv_bfloat16* base =
                (tile == 0) ? g_khi : (tile == 1) ? g_klo
                : (tile == 2) ? g_vhi : g_vlo;
            cp16(dstb + tile * KVT + row * RSF + c8 * 16,
                 base + (rb + row) * 64 + c8 * 8);
        }
        cp_commit();
    };

    prefetch_kv(0);
    cp_wait<1>();          // Q staged
    __syncthreads();

    // Q fragments (4 k-chunks of k16, hi + lo)
    uint32_t qhi[4][4], qlo[4][4];
    {
        const uint32_t qoff =
            (uint32_t)((w * 16 + (lane & 15)) * RSF + ((lane >> 4) * 16));
#pragma unroll
        for (int ks = 0; ks < 4; ++ks) {
            ldsm_x4(qhi[ks], sb + KVBUF + qoff + ks * 32);
            ldsm_x4(qlo[ks], sb + KVBUF + 128 * RSF + qoff + ks * 32);
        }
    }
    __syncthreads();       // Q reads done before kv tile 1 overwrites buf1

    float o[8][4];
#pragma unroll
    for (int i = 0; i < 8; i++)
#pragma unroll
        for (int e = 0; e < 4; e++) o[i][e] = 0.0f;
    float m0 = -1e30f, m1 = -1e30f, l0 = 0.0f, l1 = 0.0f;

    const uint32_t koff = (uint32_t)(((((lane >> 4) << 3) + (lane & 7)) * RSF) +
                                     ((lane >> 3) & 1) * 16);
    const uint32_t voff = (uint32_t)((((((lane >> 3) & 1) << 3) + (lane & 7)) * RSF) +
                                     ((lane >> 4) * 16));
    const int rw = qt * 128 + w * 16;
    const int r0 = rw + g, r1 = rw + g + 8;

    for (int j = 0; j < ntiles; ++j) {
        if (j + 1 < ntiles) { prefetch_kv(j + 1); cp_wait<1>(); }
        else cp_wait<0>();
        __syncthreads();

        const uint32_t bb = sb + (j & 1) * KVBUF;
        const bool skip = (64 * j > rw + 15);    // tile fully above diagonal
        if (!skip) {
            float sc[8][4];
#pragma unroll
            for (int i = 0; i < 8; i++)
#pragma unroll
                for (int e = 0; e < 4; e++) sc[i][e] = 0.0f;

            // S = Q K^T (split, 3 terms)
#pragma unroll
            for (int ks = 0; ks < 4; ++ks) {
#pragma unroll
                for (int ng = 0; ng < 4; ++ng) {
                    uint32_t kh[4], kl[4];
                    const uint32_t a = bb + koff + ng * (16 * RSF) + ks * 32;
                    ldsm_x4(kh, a);
                    ldsm_x4(kl, a + KVT);
                    mma16816(sc[ng * 2],     qhi[ks], kh);
                    mma16816(sc[ng * 2],     qhi[ks], kl);
                    mma16816(sc[ng * 2],     qlo[ks], kh);
                    mma16816(sc[ng * 2 + 1], qhi[ks], kh + 2);
                    mma16816(sc[ng * 2 + 1], qhi[ks], kl + 2);
                    mma16816(sc[ng * 2 + 1], qlo[ks], kh + 2);
                }
            }

            // causal mask (only diagonal-crossing tiles)
            if (64 * j + 63 > rw) {
#pragma unroll
                for (int nt = 0; nt < 8; ++nt) {
                    const int c0 = 64 * j + nt * 8 + 2 * tq;
                    if (c0 > r0)     sc[nt][0] = -1e30f;
                    if (c0 + 1 > r0) sc[nt][1] = -1e30f;
                    if (c0 > r1)     sc[nt][2] = -1e30f;
                    if (c0 + 1 > r1) sc[nt][3] = -1e30f;
                }
            }

            // online softmax (rows g, g+8; quad = lanes sharing g)
            float mx0 = -1e30f, mx1 = -1e30f;
#pragma unroll
            for (int nt = 0; nt < 8; ++nt) {
                mx0 = fmaxf(mx0, fmaxf(sc[nt][0], sc[nt][1]));
                mx1 = fmaxf(mx1, fmaxf(sc[nt][2], sc[nt][3]));
            }
            mx0 = fmaxf(mx0, __shfl_xor_sync(0xffffffffu, mx0, 1));
            mx0 = fmaxf(mx0, __shfl_xor_sync(0xffffffffu, mx0, 2));
            mx1 = fmaxf(mx1, __shfl_xor_sync(0xffffffffu, mx1, 1));
            mx1 = fmaxf(mx1, __shfl_xor_sync(0xffffffffu, mx1, 2));

            const float mn0 = fmaxf(m0, mx0), mn1 = fmaxf(m1, mx1);
            const float a0 = __expf(m0 - mn0), a1 = __expf(m1 - mn1);
            float s0 = 0.0f, s1 = 0.0f;
#pragma unroll
            for (int nt = 0; nt < 8; ++nt) {
                sc[nt][0] = __expf(sc[nt][0] - mn0);
                sc[nt][1] = __expf(sc[nt][1] - mn0);
                sc[nt][2] = __expf(sc[nt][2] - mn1);
                sc[nt][3] = __expf(sc[nt][3] - mn1);
                s0 += sc[nt][0] + sc[nt][1];
                s1 += sc[nt][2] + sc[nt][3];
            }
            s0 += __shfl_xor_sync(0xffffffffu, s0, 1);
            s0 += __shfl_xor_sync(0xffffffffu, s0, 2);
            s1 += __shfl_xor_sync(0xffffffffu, s1, 1);
            s1 += __shfl_xor_sync(0xffffffffu, s1, 2);
            l0 = l0 * a0 + s0;
            l1 = l1 * a1 + s1;
            m0 = mn0; m1 = mn1;
#pragma unroll
            for (int dt = 0; dt < 8; ++dt) {
                o[dt][0] *= a0; o[dt][1] *= a0;
                o[dt][2] *= a1; o[dt][3] *= a1;
            }

            // O += P V (P split in registers, V via ldmatrix.trans)
#pragma unroll
            for (int ks = 0; ks < 4; ++ks) {
                uint32_t phi[4], plo[4];
                pack2(sc[2 * ks][0],     sc[2 * ks][1],     phi[0], plo[0]);
                pack2(sc[2 * ks][2],     sc[2 * ks][3],     phi[1], plo[1]);
                pack2(sc[2 * ks + 1][0], sc[2 * ks + 1][1], phi[2], plo[2]);
                pack2(sc[2 * ks + 1][2], sc[2 * ks + 1][3], phi[3], plo[3]);
#pragma unroll
                for (int dl = 0; dl < 4; ++dl) {
                    uint32_t vh[4], vl[4];
                    const uint32_t a =
                        bb + 2 * KVT + voff + ks * (16 * RSF) + dl * 32;
                    ldsm_x4_t(vh, a);
                    ldsm_x4_t(vl, a + KVT);
                    mma16816(o[dl * 2],     phi, vh);
                    mma16816(o[dl * 2],     phi, vl);
                    mma16816(o[dl * 2],     plo, vh);
                    mma16816(o[dl * 2 + 1], phi, vh + 2);
                    mma16816(o[dl * 2 + 1], phi, vl + 2);
                    mma16816(o[dl * 2 + 1], plo, vh + 2);
                }
            }
        }
        __syncthreads();
    }

    // Epilogue: write y hi/lo directly
    const float inv0 = 1.0f / l0, inv1 = 1.0f / l1;
    const int b = bh >> 4, h = bh & 15;
#pragma unroll
    for (int dt = 0; dt < 8; ++dt) {
        uint32_t hh, ll;
        const size_t i0 = ((size_t)b * TT + r0) * CC + h * 64 + dt * 8 + 2 * tq;
        const size_t i1 = ((size_t)b * TT + r1) * CC + h * 64 + dt * 8 + 2 * tq;
        pack2(o[dt][0] * inv0, o[dt][1] * inv0, hh, ll);
        *(uint32_t*)(g_y_hi + i0) = hh;
        *(uint32_t*)(g_y_lo + i0) = ll;
        pack2(o[dt][2] * inv1, o[dt][3] * inv1, hh, ll);
        *(uint32_t*)(g_y_hi + i1) = hh;
        *(uint32_t*)(g_y_lo + i1) = ll;
    }
}

// ---------------------------------------------------------------------------
// Launch
// ---------------------------------------------------------------------------
extern "C" void kernel_launch(void* const* d_in, const int* in_sizes, int n_in,
                              void* d_out, int out_size)
{
    const float* x        = (const float*)d_in[0];
    const float* qkv_w    = (const float*)d_in[1];
    const float* c_proj_w = (const float*)d_in[2];
    const float* c_proj_b = (const float*)d_in[3];
    float* out = (float*)d_out;

    cudaFuncSetAttribute(gemm_tc<0>,
                         cudaFuncAttributeMaxDynamicSharedMemorySize, GEMM_SMEM);
    cudaFuncSetAttribute(gemm_tc<1>,
                         cudaFuncAttributeMaxDynamicSharedMemorySize, GEMM_SMEM);
    cudaFuncSetAttribute(flash_tc,
                         cudaFuncAttributeMaxDynamicSharedMemorySize, FSMEM);

    // 0. split fp32 -> bf16 hi/lo for x, qkv_w, c_proj_w
    split_k<0><<<(MTOT * CC) / 2048, 256>>>(x);
    split_k<1><<<(NQKV * CC) / 2048, 256>>>(qkv_w);
    split_k<2><<<(CC * CC) / 2048, 256>>>(c_proj_w);

    // 1. QKV projection (HMMA bf16x3): q,k fp32; v directly bf16 hi/lo
    gemm_tc<0><<<dim3(NQKV / 128, MTOT / 128), 256, GEMM_SMEM>>>(
        nullptr, nullptr, NQKV);

    // 2. RoPE in-place on fp32 q,k
    rope_kernel<<<(BB * HH * TT * 16) / 256, 256>>>();

    // 3. q (scaled), k -> bf16 hi/lo
    qk_split<1><<<(BB * HH * TT * DD) / 2048, 256>>>();
    qk_split<0><<<(BB * HH * TT * DD) / 2048, 256>>>();

    // 4. Causal flash attention (HMMA) -> y hi/lo
    flash_tc<<<dim3(TT / 128, BB * HH), 256, FSMEM>>>();

    // 5. Output projection (HMMA bf16x3) + bias -> d_out
    gemm_tc<1><<<dim3(CC / 128, MTOT / 128), 256, GEMM_SMEM>>>(
        c_proj_b, out, CC);
}

// round 14
// speedup vs baseline: 1.0003x; 1.0003x over previous
#include <cuda_runtime.h>
#include <cuda_bf16.h>
#include <math.h>
#include <stdint.h>

// Problem shape (fixed by the reference)
constexpr int BB = 4;
constexpr int TT = 2048;
constexpr int CC = 1024;
constexpr int HH = 16;
constexpr int DD = 64;
constexpr int MTOT = BB * TT;     // 8192
constexpr int NQKV = 3 * CC;      // 3072
constexpr int KDIM = CC;          // 1024

// ---------------------------------------------------------------------------
// Scratch (device globals — no allocation allowed)
// ---------------------------------------------------------------------------
__device__ __align__(16) float g_q[(size_t)BB * HH * TT * DD];   // [B,H,T,D] fp32
__device__ __align__(16) float g_k[(size_t)BB * HH * TT * DD];

// bf16 split-precision copies (hi + lo)
__device__ __align__(16) __nv_bfloat16 g_x_hi[(size_t)MTOT * CC];
__device__ __align__(16) __nv_bfloat16 g_x_lo[(size_t)MTOT * CC];
__device__ __align__(16) __nv_bfloat16 g_w_hi[(size_t)NQKV * CC];
__device__ __align__(16) __nv_bfloat16 g_w_lo[(size_t)NQKV * CC];
__device__ __align__(16) __nv_bfloat16 g_pw_hi[(size_t)CC * CC];
__device__ __align__(16) __nv_bfloat16 g_pw_lo[(size_t)CC * CC];
__device__ __align__(16) __nv_bfloat16 g_y_hi[(size_t)MTOT * CC];
__device__ __align__(16) __nv_bfloat16 g_y_lo[(size_t)MTOT * CC];

// attention operands in bf16 hi/lo, [B,H,T,D]
__device__ __align__(16) __nv_bfloat16 g_qhi[(size_t)BB * HH * TT * DD];
__device__ __align__(16) __nv_bfloat16 g_qlo[(size_t)BB * HH * TT * DD];
__device__ __align__(16) __nv_bfloat16 g_khi[(size_t)BB * HH * TT * DD];
__device__ __align__(16) __nv_bfloat16 g_klo[(size_t)BB * HH * TT * DD];
__device__ __align__(16) __nv_bfloat16 g_vhi[(size_t)BB * HH * TT * DD];
__device__ __align__(16) __nv_bfloat16 g_vlo[(size_t)BB * HH * TT * DD];

// ---------------------------------------------------------------------------
// PTX helpers (compute_103-safe: mma.sync / ldmatrix / cp.async only)
// ---------------------------------------------------------------------------
__device__ __forceinline__ uint32_t smem_u32(const void* p) {
    uint32_t a;
    asm("{ .reg .u64 t; cvta.to.shared.u64 t, %1; cvt.u32.u64 %0, t; }"
        : "=r"(a) : "l"(p));
    return a;
}
__device__ __forceinline__ void cp16(uint32_t dst, const void* src) {
    asm volatile("cp.async.cg.shared.global [%0], [%1], 16;"
                 :: "r"(dst), "l"(src) : "memory");
}
__device__ __forceinline__ void cp_commit() {
    asm volatile("cp.async.commit_group;" ::: "memory");
}
template <int N>
__device__ __forceinline__ void cp_wait() {
    asm volatile("cp.async.wait_group %0;" :: "n"(N) : "memory");
}
__device__ __forceinline__ void ldsm_x4(uint32_t* r, uint32_t addr) {
    asm volatile("ldmatrix.sync.aligned.m8n8.x4.shared.b16 {%0,%1,%2,%3}, [%4];"
                 : "=r"(r[0]), "=r"(r[1]), "=r"(r[2]), "=r"(r[3]) : "r"(addr));
}
__device__ __forceinline__ void ldsm_x4_t(uint32_t* r, uint32_t addr) {
    asm volatile("ldmatrix.sync.aligned.m8n8.x4.trans.shared.b16 {%0,%1,%2,%3}, [%4];"
                 : "=r"(r[0]), "=r"(r[1]), "=r"(r[2]), "=r"(r[3]) : "r"(addr));
}
__device__ __forceinline__ void mma16816(float* c, const uint32_t* a,
                                         const uint32_t* b) {
    asm volatile(
        "mma.sync.aligned.m16n8k16.row.col.f32.bf16.bf16.f32 "
        "{%0,%1,%2,%3}, {%4,%5,%6,%7}, {%8,%9}, {%0,%1,%2,%3};"
        : "+f"(c[0]), "+f"(c[1]), "+f"(c[2]), "+f"(c[3])
        : "r"(a[0]), "r"(a[1]), "r"(a[2]), "r"(a[3]), "r"(b[0]), "r"(b[1]));
}
// Split a float pair into packed bf16 hi and bf16 lo (low half = first elem)
__device__ __forceinline__ void pack2(float a, float b, uint32_t& hi, uint32_t& lo) {
    __nv_bfloat162 h = __floats2bfloat162_rn(a, b);
    __nv_bfloat162 l = __floats2bfloat162_rn(a - __bfloat162float(h.x),
                                             b - __bfloat162float(h.y));
    hi = *(uint32_t*)&h;
    lo = *(uint32_t*)&l;
}

// ---------------------------------------------------------------------------
// Split fp32 -> bf16 hi + bf16 lo.  W selects the (dst hi, dst lo) pair.
// ---------------------------------------------------------------------------
template <int W>
__global__ __launch_bounds__(256) void split_k(const float* __restrict__ s)
{
    __nv_bfloat16 *hi, *lo;
    if (W == 0)      { hi = g_x_hi;  lo = g_x_lo;  }
    else if (W == 1) { hi = g_w_hi;  lo = g_w_lo;  }
    else             { hi = g_pw_hi; lo = g_pw_lo; }

    const size_t base = ((size_t)blockIdx.x * 256 + threadIdx.x) * 8;
    float4 v0 = *(const float4*)(s + base);
    float4 v1 = *(const float4*)(s + base + 4);
    float v[8] = {v0.x, v0.y, v0.z, v0.w, v1.x, v1.y, v1.z, v1.w};
    __align__(16) __nv_bfloat16 h[8];
    __align__(16) __nv_bfloat16 l[8];
#pragma unroll
    for (int i = 0; i < 8; i++) {
        h[i] = __float2bfloat16_rn(v[i]);
        l[i] = __float2bfloat16_rn(v[i] - __bfloat162float(h[i]));
    }
    *(uint4*)(hi + base) = *(const uint4*)h;
    *(uint4*)(lo + base) = *(const uint4*)l;
}

// Split q (scaled by 1/8) or k into bf16 hi/lo after rope.
template <int IS_Q>
__global__ __launch_bounds__(256) void qk_split()
{
    const float* s = IS_Q ? g_q : g_k;
    __nv_bfloat16* hi = IS_Q ? g_qhi : g_khi;
    __nv_bfloat16* lo = IS_Q ? g_qlo : g_klo;
    const float scale = IS_Q ? 0.125f : 1.0f;
    const size_t base = ((size_t)blockIdx.x * 256 + threadIdx.x) * 8;
    float4 v0 = *(const float4*)(s + base);
    float4 v1 = *(const float4*)(s + base + 4);
    float v[8] = {v0.x, v0.y, v0.z, v0.w, v1.x, v1.y, v1.z, v1.w};
    __align__(16) __nv_bfloat16 h[8];
    __align__(16) __nv_bfloat16 l[8];
#pragma unroll
    for (int i = 0; i < 8; i++) {
        const float f = v[i] * scale;
        h[i] = __float2bfloat16_rn(f);
        l[i] = __float2bfloat16_rn(f - __bfloat162float(h[i]));
    }
    *(uint4*)(hi + base) = *(const uint4*)h;
    *(uint4*)(lo + base) = *(const uint4*)l;
}

// ---------------------------------------------------------------------------
// HMMA bf16x3 GEMM: C[M,N] = A[M,K] * B[N,K]^T in split precision.
// BM=BN=128, BK=32. 8 warps (2x4), each 64x32. Double-buffered cp.async.
// MODE 0: q,k fp32 scatter; v written directly as bf16 hi/lo.
// MODE 1: +bias -> out.
// ---------------------------------------------------------------------------
constexpr int BK = 32;
constexpr int NC = KDIM / BK;              // 32 k-chunks
constexpr int RS = 80;                     // smem row stride (bytes)
constexpr int TILE_B = 128 * RS;           // 10240 B per tile
constexpr int BUF_B = 4 * TILE_B;          // Ah, Al, Bh, Bl = 40960 B
constexpr int GEMM_SMEM = 2 * BUF_B;       // 81920 B

template <int MODE>
__global__ __launch_bounds__(256, 1)
void gemm_tc(const float* __restrict__ bias, float* __restrict__ out, int N)
{
    extern __shared__ char sp[];
    const uint32_t sb = smem_u32(sp);

    const int tid  = threadIdx.x;
    const int wid  = tid >> 5;
    const int lane = tid & 31;
    const int wm   = wid >> 2;
    const int wn   = wid & 3;
    const int tileM = blockIdx.y * 128;
    const int tileN = blockIdx.x * 128;

    const __nv_bfloat16* Ah = (MODE == 0) ? g_x_hi : g_y_hi;
    const __nv_bfloat16* Al = (MODE == 0) ? g_x_lo : g_y_lo;
    const __nv_bfloat16* Bh = (MODE == 0) ? g_w_hi : g_pw_hi;
    const __nv_bfloat16* Bl = (MODE == 0) ? g_w_lo : g_pw_lo;

    const int lrow = tid >> 1;
    const int lcb  = (tid & 1) * 2;
    const size_t gA = (size_t)(tileM + lrow) * KDIM + lcb * 8;
    const size_t gB = (size_t)(tileN + lrow) * KDIM + lcb * 8;
    const uint32_t sOff = (uint32_t)(lrow * RS + lcb * 16);

    auto prefetch = [&](int c) {
        const uint32_t bb = sb + (c & 1) * BUF_B;
        const int k0 = c * BK;
        cp16(bb + sOff,                Ah + gA + k0);
        cp16(bb + sOff + 16,           Ah + gA + k0 + 8);
        cp16(bb + TILE_B + sOff,       Al + gA + k0);
        cp16(bb + TILE_B + sOff + 16,  Al + gA + k0 + 8);
        cp16(bb + 2 * TILE_B + sOff,      Bh + gB + k0);
        cp16(bb + 2 * TILE_B + sOff + 16, Bh + gB + k0 + 8);
        cp16(bb + 3 * TILE_B + sOff,      Bl + gB + k0);
        cp16(bb + 3 * TILE_B + sOff + 16, Bl + gB + k0 + 8);
        cp_commit();
    };

    const uint32_t aoff = (uint32_t)((wm * 64 + (lane & 15)) * RS +
                                     ((lane >> 4) * 16));
    const uint32_t boff = (uint32_t)((wn * 32 + ((lane >> 4) << 3) + (lane & 7)) * RS +
                                     (((lane >> 3) & 1) * 16));

    float acc[4][4][4];
#pragma unroll
    for (int i = 0; i < 4; i++)
#pragma unroll
        for (int j = 0; j < 4; j++)
#pragma unroll
            for (int e = 0; e < 4; e++) acc[i][j][e] = 0.0f;

    prefetch(0);

    for (int c = 0; c < NC; ++c) {
        if (c + 1 < NC) prefetch(c + 1);
        if (c + 1 < NC) cp_wait<1>(); else cp_wait<0>();
        __syncthreads();

        const uint32_t bb = sb + (c & 1) * BUF_B;
#pragma unroll
        for (int ks = 0; ks < 2; ++ks) {
            const uint32_t kb = ks * 32;
            uint32_t ah[4][4], al[4][4], bh[2][4], bl[2][4];
#pragma unroll
            for (int mi = 0; mi < 4; ++mi) {
                ldsm_x4(ah[mi], bb + aoff + mi * (16 * RS) + kb);
                ldsm_x4(al[mi], bb + TILE_B + aoff + mi * (16 * RS) + kb);
            }
#pragma unroll
            for (int n2 = 0; n2 < 2; ++n2) {
                ldsm_x4(bh[n2], bb + 2 * TILE_B + boff + n2 * (16 * RS) + kb);
                ldsm_x4(bl[n2], bb + 3 * TILE_B + boff + n2 * (16 * RS) + kb);
            }
#pragma unroll
            for (int mi = 0; mi < 4; ++mi)
#pragma unroll
                for (int ni = 0; ni < 4; ++ni) {
                    const uint32_t* bhp = &bh[ni >> 1][(ni & 1) * 2];
                    const uint32_t* blp = &bl[ni >> 1][(ni & 1) * 2];
                    mma16816(acc[mi][ni], ah[mi], bhp);
                    mma16816(acc[mi][ni], ah[mi], blp);
                    mma16816(acc[mi][ni], al[mi], bhp);
                }
        }
        __syncthreads();
    }

    const int g4 = lane >> 2;
    const int t4 = lane & 3;
#pragma unroll
    for (int mi = 0; mi < 4; ++mi) {
        const int m0 = tileM + wm * 64 + mi * 16 + g4;
#pragma unroll
        for (int ni = 0; ni < 4; ++ni) {
            const int n = tileN + wn * 32 + ni * 8 + t4 * 2;
            float2 v0 = make_float2(acc[mi][ni][0], acc[mi][ni][1]);
            float2 v1 = make_float2(acc[mi][ni][2], acc[mi][ni][3]);
            if (MODE == 0) {
                const int which = n >> 10;
                const int h = (n & 1023) >> 6;
                const int d = n & 63;
                const int m1 = m0 + 8;
                const size_t i0 =
                    (((size_t)((m0 >> 11) * HH + h)) * TT + (m0 & 2047)) * DD + d;
                const size_t i1 =
                    (((size_t)((m1 >> 11) * HH + h)) * TT + (m1 & 2047)) * DD + d;
                if (which == 2) {
                    uint32_t hh, ll;
                    pack2(v0.x, v0.y, hh, ll);
                    *(uint32_t*)(g_vhi + i0) = hh;
                    *(uint32_t*)(g_vlo + i0) = ll;
                    pack2(v1.x, v1.y, hh, ll);
                    *(uint32_t*)(g_vhi + i1) = hh;
                    *(uint32_t*)(g_vlo + i1) = ll;
                } else {
                    float* dst = (which == 0) ? g_q : g_k;
                    *(float2*)&dst[i0] = v0;
                    *(float2*)&dst[i1] = v1;
                }
            } else {
                const float2 bv = *(const float2*)&bias[n];
                v0.x += bv.x; v0.y += bv.y;
                v1.x += bv.x; v1.y += bv.y;
                *(float2*)&out[(size_t)m0 * N + n] = v0;
                *(float2*)&out[(size_t)(m0 + 8) * N + n] = v1;
            }
        }
    }
}

// ---------------------------------------------------------------------------
// RoPE in-place on g_q and g_k (only 16 nonzero-frequency pairs per head).
// ---------------------------------------------------------------------------
__global__ void rope_kernel()
{
    const int idx = blockIdx.x * blockDim.x + threadIdx.x;
    const int p = idx & 15;
    const int t = (idx >> 4) & (TT - 1);
    const int bh = idx >> 15;

    const float af = (float)pow(1.0 / 1024.0, (double)p / 15.0);
    const float theta = (float)t * af;
    double sd, cd;
    sincos((double)theta, &sd, &cd);
    const float c = (float)cd, s = (float)sd;

    const size_t base = ((size_t)bh * TT + t) * DD;
    const float q1 = g_q[base + p], q2 = g_q[base + p + 32];
    g_q[base + p]      = q1 * c + q2 * s;
    g_q[base + p + 32] = -q1 * s + q2 * c;
    const float k1 = g_k[base + p], k2 = g_k[base + p + 32];
    g_k[base + p]      = k1 * c + k2 * s;
    g_k[base + p + 32] = -k1 * s + k2 * c;
}

// ---------------------------------------------------------------------------
// Flash attention on HMMA, causal. Br=128 (8 warps x m16), Bc=64.
// Q fragments in registers; K/V hi/lo double-buffered via cp.async.
// S = Qhi Khi + Qhi Klo + Qlo Khi; P split in registers; O += Phi Vhi + ...
// Writes y directly as bf16 hi/lo for the projection GEMM.
// ---------------------------------------------------------------------------
constexpr int RSF = 144;                    // 128B data + 16B pad
constexpr int KVT = 64 * RSF;               // 9216 B per 64x64 bf16 tile
constexpr int KVBUF = 4 * KVT;              // Khi,Klo,Vhi,Vlo = 36864 B
constexpr int FSMEM = 2 * KVBUF;            // 73728 B

__global__ __launch_bounds__(256, 1)
void flash_tc()
{
    extern __shared__ char sp[];
    const uint32_t sb = smem_u32(sp);
    const int qt = 15 - blockIdx.x;         // heavy tiles first
    const int bh = blockIdx.y;
    const int tid = threadIdx.x;
    const int w = tid >> 5;
    const int lane = tid & 31;
    const int g = lane >> 2;
    const int tq = lane & 3;
    const int ntiles = 2 * qt + 2;

    // Stage Q hi/lo into buffer-1 region (reused for kv tile 1 later)
    {
        const size_t qb = ((size_t)bh * TT + (size_t)qt * 128) * DD;
#pragma unroll
        for (int t = 0; t < 8; ++t) {
            const int half = t >> 2;                  // 0: hi, 1: lo
            const int within = (t & 3) * 256 + tid;   // 0..1023
            const int row = within >> 3, c8 = within & 7;
            const __nv_bfloat16* src =
                (half ? g_qlo : g_qhi) + qb + row * 64 + c8 * 8;
            cp16(sb + KVBUF + half * (128 * RSF) + row * RSF + c8 * 16, src);
        }
        cp_commit();
    }

    auto prefetch_kv = [&](int j) {
        const uint32_t dstb = sb + (j & 1) * KVBUF;
        const size_t rb = (size_t)bh * TT + (size_t)j * 64;
#pragma unroll
        for (int t = 0; t < 8; ++t) {
            const int tile = t >> 1;                  // 0..3
            const int within = (t & 1) * 256 + tid;   // 0..511
            const int row = within >> 3, c8 = within & 7;
            const __nv_bfloat16* base =
                (tile == 0) ? g_khi : (tile == 1) ? g_klo
                : (tile == 2) ? g_vhi : g_vlo;
            cp16(dstb + tile * KVT + row * RSF + c8 * 16,
                 base + (rb + row) * 64 + c8 * 8);
        }
        cp_commit();
    };

    prefetch_kv(0);
    cp_wait<1>();          // Q staged
    __syncthreads();

    // Q fragments (4 k-chunks of k16, hi + lo)
    uint32_t qhi[4][4], qlo[4][4];
    {
        const uint32_t qoff =
            (uint32_t)((w * 16 + (lane & 15)) * RSF + ((lane >> 4) * 16));
#pragma unroll
        for (int ks = 0; ks < 4; ++ks) {
            ldsm_x4(qhi[ks], sb + KVBUF + qoff + ks * 32);
            ldsm_x4(qlo[ks], sb + KVBUF + 128 * RSF + qoff + ks * 32);
        }
    }
    __syncthreads();       // Q reads done before kv tile 1 overwrites buf1

    float o[8][4];
#pragma unroll
    for (int i = 0; i < 8; i++)
#pragma unroll
        for (int e = 0; e < 4; e++) o[i][e] = 0.0f;
    float m0 = -1e30f, m1 = -1e30f, l0 = 0.0f, l1 = 0.0f;

    const uint32_t koff = (uint32_t)(((((lane >> 4) << 3) + (lane & 7)) * RSF) +
                                     ((lane >> 3) & 1) * 16);
    const uint32_t voff = (uint32_t)((((((lane >> 3) & 1) << 3) + (lane & 7)) * RSF) +
                                     ((lane >> 4) * 16));
    const int rw = qt * 128 + w * 16;
    const int r0 = rw + g, r1 = rw + g + 8;

    for (int j = 0; j < ntiles; ++j) {
        if (j + 1 < ntiles) { prefetch_kv(j + 1); cp_wait<1>(); }
        else cp_wait<0>();
        __syncthreads();

        const uint32_t bb = sb + (j & 1) * KVBUF;
        const bool skip = (64 * j > rw + 15);    // tile fully above diagonal
        if (!skip) {
            float sc[8][4];
#pragma unroll
            for (int i = 0; i < 8; i++)
#pragma unroll
                for (int e = 0; e < 4; e++) sc[i][e] = 0.0f;

            // S = Q K^T (split, 3 terms)
#pragma unroll
            for (int ks = 0; ks < 4; ++ks) {
#pragma unroll
                for (int ng = 0; ng < 4; ++ng) {
                    uint32_t kh[4], kl[4];
                    const uint32_t a = bb + koff + ng * (16 * RSF) + ks * 32;
                    ldsm_x4(kh, a);
                    ldsm_x4(kl, a + KVT);
                    mma16816(sc[ng * 2],     qhi[ks], kh);
                    mma16816(sc[ng * 2],     qhi[ks], kl);
                    mma16816(sc[ng * 2],     qlo[ks], kh);
                    mma16816(sc[ng * 2 + 1], qhi[ks], kh + 2);
                    mma16816(sc[ng * 2 + 1], qhi[ks], kl + 2);
                    mma16816(sc[ng * 2 + 1], qlo[ks], kh + 2);
                }
            }

            // causal mask (only diagonal-crossing tiles)
            if (64 * j + 63 > rw) {
#pragma unroll
                for (int nt = 0; nt < 8; ++nt) {
                    const int c0 = 64 * j + nt * 8 + 2 * tq;
                    if (c0 > r0)     sc[nt][0] = -1e30f;
                    if (c0 + 1 > r0) sc[nt][1] = -1e30f;
                    if (c0 > r1)     sc[nt][2] = -1e30f;
                    if (c0 + 1 > r1) sc[nt][3] = -1e30f;
                }
            }

            // online softmax (rows g, g+8; quad = lanes sharing g)
            float mx0 = -1e30f, mx1 = -1e30f;
#pragma unroll
            for (int nt = 0; nt < 8; ++nt) {
                mx0 = fmaxf(mx0, fmaxf(sc[nt][0], sc[nt][1]));
                mx1 = fmaxf(mx1, fmaxf(sc[nt][2], sc[nt][3]));
            }
            mx0 = fmaxf(mx0, __shfl_xor_sync(0xffffffffu, mx0, 1));
            mx0 = fmaxf(mx0, __shfl_xor_sync(0xffffffffu, mx0, 2));
            mx1 = fmaxf(mx1, __shfl_xor_sync(0xffffffffu, mx1, 1));
            mx1 = fmaxf(mx1, __shfl_xor_sync(0xffffffffu, mx1, 2));

            const float mn0 = fmaxf(m0, mx0), mn1 = fmaxf(m1, mx1);
            const float a0 = __expf(m0 - mn0), a1 = __expf(m1 - mn1);
            float s0 = 0.0f, s1 = 0.0f;
#pragma unroll
            for (int nt = 0; nt < 8; ++nt) {
                sc[nt][0] = __expf(sc[nt][0] - mn0);
                sc[nt][1] = __expf(sc[nt][1] - mn0);
                sc[nt][2] = __expf(sc[nt][2] - mn1);
                sc[nt][3] = __expf(sc[nt][3] - mn1);
                s0 += sc[nt][0] + sc[nt][1];
                s1 += sc[nt][2] + sc[nt][3];
            }
            s0 += __shfl_xor_sync(0xffffffffu, s0, 1);
            s0 += __shfl_xor_sync(0xffffffffu, s0, 2);
            s1 += __shfl_xor_sync(0xffffffffu, s1, 1);
            s1 += __shfl_xor_sync(0xffffffffu, s1, 2);
            l0 = l0 * a0 + s0;
            l1 = l1 * a1 + s1;
            m0 = mn0; m1 = mn1;
#pragma unroll
            for (int dt = 0; dt < 8; ++dt) {
                o[dt][0] *= a0; o[dt][1] *= a0;
                o[dt][2] *= a1; o[dt][3] *= a1;
            }

            // O += P V (P split in registers, V via ldmatrix.trans)
#pragma unroll
            for (int ks = 0; ks < 4; ++ks) {
                uint32_t phi[4], plo[4];
                pack2(sc[2 * ks][0],     sc[2 * ks][1],     phi[0], plo[0]);
                pack2(sc[2 * ks][2],     sc[2 * ks][3],     phi[1], plo[1]);
                pack2(sc[2 * ks + 1][0], sc[2 * ks + 1][1], phi[2], plo[2]);
                pack2(sc[2 * ks + 1][2], sc[2 * ks + 1][3], phi[3], plo[3]);
#pragma unroll
                for (int dl = 0; dl < 4; ++dl) {
                    uint32_t vh[4], vl[4];
                    const uint32_t a =
                        bb + 2 * KVT + voff + ks * (16 * RSF) + dl * 32;
                    ldsm_x4_t(vh, a);
                    ldsm_x4_t(vl, a + KVT);
                    mma16816(o[dl * 2],     phi, vh);
                    mma16816(o[dl * 2],     phi, vl);
                    mma16816(o[dl * 2],     plo, vh);
                    mma16816(o[dl * 2 + 1], phi, vh + 2);
                    mma16816(o[dl * 2 + 1], phi, vl + 2);
                    mma16816(o[dl * 2 + 1], plo, vh + 2);
                }
            }
        }
        __syncthreads();
    }

    // Epilogue: write y hi/lo directly
    const float inv0 = 1.0f / l0, inv1 = 1.0f / l1;
    const int b = bh >> 4, h = bh & 15;
#pragma unroll
    for (int dt = 0; dt < 8; ++dt) {
        uint32_t hh, ll;
        const size_t i0 = ((size_t)b * TT + r0) * CC + h * 64 + dt * 8 + 2 * tq;
        const size_t i1 = ((size_t)b * TT + r1) * CC + h * 64 + dt * 8 + 2 * tq;
        pack2(o[dt][0] * inv0, o[dt][1] * inv0, hh, ll);
        *(uint32_t*)(g_y_hi + i0) = hh;
        *(uint32_t*)(g_y_lo + i0) = ll;
        pack2(o[dt][2] * inv1, o[dt][3] * inv1, hh, ll);
        *(uint32_t*)(g_y_hi + i1) = hh;
        *(uint32_t*)(g_y_lo + i1) = ll;
    }
}

// ---------------------------------------------------------------------------
// Launch
// ---------------------------------------------------------------------------
extern "C" void kernel_launch(void* const* d_in, const int* in_sizes, int n_in,
                              void* d_out, int out_size)
{
    const float* x        = (const float*)d_in[0];
    const float* qkv_w    = (const float*)d_in[1];
    const float* c_proj_w = (const float*)d_in[2];
    const float* c_proj_b = (const float*)d_in[3];
    float* out = (float*)d_out;

    cudaFuncSetAttribute(gemm_tc<0>,
                         cudaFuncAttributeMaxDynamicSharedMemorySize, GEMM_SMEM);
    cudaFuncSetAttribute(gemm_tc<1>,
                         cudaFuncAttributeMaxDynamicSharedMemorySize, GEMM_SMEM);
    cudaFuncSetAttribute(flash_tc,
                         cudaFuncAttributeMaxDynamicSharedMemorySize, FSMEM);

    // 0. split fp32 -> bf16 hi/lo for x, qkv_w, c_proj_w
    split_k<0><<<(MTOT * CC) / 2048, 256>>>(x);
    split_k<1><<<(NQKV * CC) / 2048, 256>>>(qkv_w);
    split_k<2><<<(CC * CC) / 2048, 256>>>(c_proj_w);

    // 1. QKV projection (HMMA bf16x3): q,k fp32; v directly bf16 hi/lo
    gemm_tc<0><<<dim3(NQKV / 128, MTOT / 128), 256, GEMM_SMEM>>>(
        nullptr, nullptr, NQKV);

    // 2. RoPE in-place on fp32 q,k
    rope_kernel<<<(BB * HH * TT * 16) / 256, 256>>>();

    // 3. q (scaled), k -> bf16 hi/lo
    qk_split<1><<<(BB * HH * TT * DD) / 2048, 256>>>();
    qk_split<0><<<(BB * HH * TT * DD) / 2048, 256>>>();

    // 4. Causal flash attention (HMMA) -> y hi/lo
    flash_tc<<<dim3(TT / 128, BB * HH), 256, FSMEM>>>();

    // 5. Output projection (HMMA bf16x3) + bias -> d_out
    gemm_tc<1><<<dim3(CC / 128, MTOT / 128), 256, GEMM_SMEM>>>(
        c_proj_b, out, CC);
}

// round 15
// speedup vs baseline: 1.0003x; 1.0000x over previous
#include <cuda_runtime.h>
#include <cuda_bf16.h>
#include <math.h>
#include <stdint.h>

// Problem shape (fixed by the reference)
constexpr int BB = 4;
constexpr int TT = 2048;
constexpr int CC = 1024;
constexpr int HH = 16;
constexpr int DD = 64;
constexpr int MTOT = BB * TT;     // 8192
constexpr int NQKV = 3 * CC;      // 3072
constexpr int KDIM = CC;          // 1024

// ---------------------------------------------------------------------------
// Scratch (device globals — no allocation allowed)
// ---------------------------------------------------------------------------
__device__ __align__(16) float g_q[(size_t)BB * HH * TT * DD];   // [B,H,T,D] fp32
__device__ __align__(16) float g_k[(size_t)BB * HH * TT * DD];

// bf16 split-precision copies (hi + lo)
__device__ __align__(16) __nv_bfloat16 g_x_hi[(size_t)MTOT * CC];
__device__ __align__(16) __nv_bfloat16 g_x_lo[(size_t)MTOT * CC];
__device__ __align__(16) __nv_bfloat16 g_w_hi[(size_t)NQKV * CC];
__device__ __align__(16) __nv_bfloat16 g_w_lo[(size_t)NQKV * CC];
__device__ __align__(16) __nv_bfloat16 g_pw_hi[(size_t)CC * CC];
__device__ __align__(16) __nv_bfloat16 g_pw_lo[(size_t)CC * CC];
__device__ __align__(16) __nv_bfloat16 g_y_hi[(size_t)MTOT * CC];
__device__ __align__(16) __nv_bfloat16 g_y_lo[(size_t)MTOT * CC];

// attention operands in bf16 hi/lo, [B,H,T,D]
__device__ __align__(16) __nv_bfloat16 g_qhi[(size_t)BB * HH * TT * DD];
__device__ __align__(16) __nv_bfloat16 g_qlo[(size_t)BB * HH * TT * DD];
__device__ __align__(16) __nv_bfloat16 g_khi[(size_t)BB * HH * TT * DD];
__device__ __align__(16) __nv_bfloat16 g_klo[(size_t)BB * HH * TT * DD];
__device__ __align__(16) __nv_bfloat16 g_vhi[(size_t)BB * HH * TT * DD];
__device__ __align__(16) __nv_bfloat16 g_vlo[(size_t)BB * HH * TT * DD];

// ---------------------------------------------------------------------------
// PTX helpers (compute_103-safe: mma.sync / ldmatrix / cp.async only)
// ---------------------------------------------------------------------------
__device__ __forceinline__ uint32_t smem_u32(const void* p) {
    uint32_t a;
    asm("{ .reg .u64 t; cvta.to.shared.u64 t, %1; cvt.u32.u64 %0, t; }"
        : "=r"(a) : "l"(p));
    return a;
}
__device__ __forceinline__ void cp16(uint32_t dst, const void* src) {
    asm volatile("cp.async.cg.shared.global [%0], [%1], 16;"
                 :: "r"(dst), "l"(src) : "memory");
}
__device__ __forceinline__ void cp_commit() {
    asm volatile("cp.async.commit_group;" ::: "memory");
}
template <int N>
__device__ __forceinline__ void cp_wait() {
    asm volatile("cp.async.wait_group %0;" :: "n"(N) : "memory");
}
__device__ __forceinline__ void ldsm_x4(uint32_t* r, uint32_t addr) {
    asm volatile("ldmatrix.sync.aligned.m8n8.x4.shared.b16 {%0,%1,%2,%3}, [%4];"
                 : "=r"(r[0]), "=r"(r[1]), "=r"(r[2]), "=r"(r[3]) : "r"(addr));
}
__device__ __forceinline__ void ldsm_x4_t(uint32_t* r, uint32_t addr) {
    asm volatile("ldmatrix.sync.aligned.m8n8.x4.trans.shared.b16 {%0,%1,%2,%3}, [%4];"
                 : "=r"(r[0]), "=r"(r[1]), "=r"(r[2]), "=r"(r[3]) : "r"(addr));
}
__device__ __forceinline__ void mma16816(float* c, const uint32_t* a,
                                         const uint32_t* b) {
    asm volatile(
        "mma.sync.aligned.m16n8k16.row.col.f32.bf16.bf16.f32 "
        "{%0,%1,%2,%3}, {%4,%5,%6,%7}, {%8,%9}, {%0,%1,%2,%3};"
        : "+f"(c[0]), "+f"(c[1]), "+f"(c[2]), "+f"(c[3])
        : "r"(a[0]), "r"(a[1]), "r"(a[2]), "r"(a[3]), "r"(b[0]), "r"(b[1]));
}
// Split a float pair into packed bf16 hi and bf16 lo (low half = first elem)
__device__ __forceinline__ void pack2(float a, float b, uint32_t& hi, uint32_t& lo) {
    __nv_bfloat162 h = __floats2bfloat162_rn(a, b);
    __nv_bfloat162 l = __floats2bfloat162_rn(a - __bfloat162float(h.x),
                                             b - __bfloat162float(h.y));
    hi = *(uint32_t*)&h;
    lo = *(uint32_t*)&l;
}

// ---------------------------------------------------------------------------
// Split fp32 -> bf16 hi + bf16 lo.  W selects the (dst hi, dst lo) pair.
// ---------------------------------------------------------------------------
template <int W>
__global__ __launch_bounds__(256) void split_k(const float* __restrict__ s)
{
    __nv_bfloat16 *hi, *lo;
    if (W == 0)      { hi = g_x_hi;  lo = g_x_lo;  }
    else if (W == 1) { hi = g_w_hi;  lo = g_w_lo;  }
    else             { hi = g_pw_hi; lo = g_pw_lo; }

    const size_t base = ((size_t)blockIdx.x * 256 + threadIdx.x) * 8;
    float4 v0 = *(const float4*)(s + base);
    float4 v1 = *(const float4*)(s + base + 4);
    float v[8] = {v0.x, v0.y, v0.z, v0.w, v1.x, v1.y, v1.z, v1.w};
    __align__(16) __nv_bfloat16 h[8];
    __align__(16) __nv_bfloat16 l[8];
#pragma unroll
    for (int i = 0; i < 8; i++) {
        h[i] = __float2bfloat16_rn(v[i]);
        l[i] = __float2bfloat16_rn(v[i] - __bfloat162float(h[i]));
    }
    *(uint4*)(hi + base) = *(const uint4*)h;
    *(uint4*)(lo + base) = *(const uint4*)l;
}

// Split q (scaled by 1/8) or k into bf16 hi/lo after rope.
template <int IS_Q>
__global__ __launch_bounds__(256) void qk_split()
{
    const float* s = IS_Q ? g_q : g_k;
    __nv_bfloat16* hi = IS_Q ? g_qhi : g_khi;
    __nv_bfloat16* lo = IS_Q ? g_qlo : g_klo;
    const float scale = IS_Q ? 0.125f : 1.0f;
    const size_t base = ((size_t)blockIdx.x * 256 + threadIdx.x) * 8;
    float4 v0 = *(const float4*)(s + base);
    float4 v1 = *(const float4*)(s + base + 4);
    float v[8] = {v0.x, v0.y, v0.z, v0.w, v1.x, v1.y, v1.z, v1.w};
    __align__(16) __nv_bfloat16 h[8];
    __align__(16) __nv_bfloat16 l[8];
#pragma unroll
    for (int i = 0; i < 8; i++) {
        const float f = v[i] * scale;
        h[i] = __float2bfloat16_rn(f);
        l[i] = __float2bfloat16_rn(f - __bfloat162float(h[i]));
    }
    *(uint4*)(hi + base) = *(const uint4*)h;
    *(uint4*)(lo + base) = *(const uint4*)l;
}

// ---------------------------------------------------------------------------
// HMMA bf16x3 GEMM: C[M,N] = A[M,K] * B[N,K]^T in split precision.
// BM=BN=128, BK=32. 8 warps (2x4), each 64x32. Double-buffered cp.async.
// MODE 0: q,k fp32 scatter; v written directly as bf16 hi/lo.
// MODE 1: +bias -> out.
// ---------------------------------------------------------------------------
constexpr int BK = 32;
constexpr int NC = KDIM / BK;              // 32 k-chunks
constexpr int RS = 80;                     // smem row stride (bytes)
constexpr int TILE_B = 128 * RS;           // 10240 B per tile
constexpr int BUF_B = 4 * TILE_B;          // Ah, Al, Bh, Bl = 40960 B
constexpr int GEMM_SMEM = 2 * BUF_B;       // 81920 B

template <int MODE>
__global__ __launch_bounds__(256, 1)
void gemm_tc(const float* __restrict__ bias, float* __restrict__ out, int N)
{
    extern __shared__ char sp[];
    const uint32_t sb = smem_u32(sp);

    const int tid  = threadIdx.x;
    const int wid  = tid >> 5;
    const int lane = tid & 31;
    const int wm   = wid >> 2;
    const int wn   = wid & 3;
    const int tileM = blockIdx.y * 128;
    const int tileN = blockIdx.x * 128;

    const __nv_bfloat16* Ah = (MODE == 0) ? g_x_hi : g_y_hi;
    const __nv_bfloat16* Al = (MODE == 0) ? g_x_lo : g_y_lo;
    const __nv_bfloat16* Bh = (MODE == 0) ? g_w_hi : g_pw_hi;
    const __nv_bfloat16* Bl = (MODE == 0) ? g_w_lo : g_pw_lo;

    const int lrow = tid >> 1;
    const int lcb  = (tid & 1) * 2;
    const size_t gA = (size_t)(tileM + lrow) * KDIM + lcb * 8;
    const size_t gB = (size_t)(tileN + lrow) * KDIM + lcb * 8;
    const uint32_t sOff = (uint32_t)(lrow * RS + lcb * 16);

    auto prefetch = [&](int c) {
        const uint32_t bb = sb + (c & 1) * BUF_B;
        const int k0 = c * BK;
        cp16(bb + sOff,                Ah + gA + k0);
        cp16(bb + sOff + 16,           Ah + gA + k0 + 8);
        cp16(bb + TILE_B + sOff,       Al + gA + k0);
        cp16(bb + TILE_B + sOff + 16,  Al + gA + k0 + 8);
        cp16(bb + 2 * TILE_B + sOff,      Bh + gB + k0);
        cp16(bb + 2 * TILE_B + sOff + 16, Bh + gB + k0 + 8);
        cp16(bb + 3 * TILE_B + sOff,      Bl + gB + k0);
        cp16(bb + 3 * TILE_B + sOff + 16, Bl + gB + k0 + 8);
        cp_commit();
    };

    const uint32_t aoff = (uint32_t)((wm * 64 + (lane & 15)) * RS +
                                     ((lane >> 4) * 16));
    const uint32_t boff = (uint32_t)((wn * 32 + ((lane >> 4) << 3) + (lane & 7)) * RS +
                                     (((lane >> 3) & 1) * 16));

    float acc[4][4][4];
#pragma unroll
    for (int i = 0; i < 4; i++)
#pragma unroll
        for (int j = 0; j < 4; j++)
#pragma unroll
            for (int e = 0; e < 4; e++) acc[i][j][e] = 0.0f;

    prefetch(0);

    for (int c = 0; c < NC; ++c) {
        if (c + 1 < NC) prefetch(c + 1);
        if (c + 1 < NC) cp_wait<1>(); else cp_wait<0>();
        __syncthreads();

        const uint32_t bb = sb + (c & 1) * BUF_B;
#pragma unroll
        for (int ks = 0; ks < 2; ++ks) {
            const uint32_t kb = ks * 32;
            uint32_t ah[4][4], al[4][4], bh[2][4], bl[2][4];
#pragma unroll
            for (int mi = 0; mi < 4; ++mi) {
                ldsm_x4(ah[mi], bb + aoff + mi * (16 * RS) + kb);
                ldsm_x4(al[mi], bb + TILE_B + aoff + mi * (16 * RS) + kb);
            }
#pragma unroll
            for (int n2 = 0; n2 < 2; ++n2) {
                ldsm_x4(bh[n2], bb + 2 * TILE_B + boff + n2 * (16 * RS) + kb);
                ldsm_x4(bl[n2], bb + 3 * TILE_B + boff + n2 * (16 * RS) + kb);
            }
#pragma unroll
            for (int mi = 0; mi < 4; ++mi)
#pragma unroll
                for (int ni = 0; ni < 4; ++ni) {
                    const uint32_t* bhp = &bh[ni >> 1][(ni & 1) * 2];
                    const uint32_t* blp = &bl[ni >> 1][(ni & 1) * 2];
                    mma16816(acc[mi][ni], ah[mi], bhp);
                    mma16816(acc[mi][ni], ah[mi], blp);
                    mma16816(acc[mi][ni], al[mi], bhp);
                }
        }
        __syncthreads();
    }

    const int g4 = lane >> 2;
    const int t4 = lane & 3;
#pragma unroll
    for (int mi = 0; mi < 4; ++mi) {
        const int m0 = tileM + wm * 64 + mi * 16 + g4;
#pragma unroll
        for (int ni = 0; ni < 4; ++ni) {
            const int n = tileN + wn * 32 + ni * 8 + t4 * 2;
            float2 v0 = make_float2(acc[mi][ni][0], acc[mi][ni][1]);
            float2 v1 = make_float2(acc[mi][ni][2], acc[mi][ni][3]);
            if (MODE == 0) {
                const int which = n >> 10;
                const int h = (n & 1023) >> 6;
                const int d = n & 63;
                const int m1 = m0 + 8;
                const size_t i0 =
                    (((size_t)((m0 >> 11) * HH + h)) * TT + (m0 & 2047)) * DD + d;
                const size_t i1 =
                    (((size_t)((m1 >> 11) * HH + h)) * TT + (m1 & 2047)) * DD + d;
                if (which == 2) {
                    uint32_t hh, ll;
                    pack2(v0.x, v0.y, hh, ll);
                    *(uint32_t*)(g_vhi + i0) = hh;
                    *(uint32_t*)(g_vlo + i0) = ll;
                    pack2(v1.x, v1.y, hh, ll);
                    *(uint32_t*)(g_vhi + i1) = hh;
                    *(uint32_t*)(g_vlo + i1) = ll;
                } else {
                    float* dst = (which == 0) ? g_q : g_k;
                    *(float2*)&dst[i0] = v0;
                    *(float2*)&dst[i1] = v1;
                }
            } else {
                const float2 bv = *(const float2*)&bias[n];
                v0.x += bv.x; v0.y += bv.y;
                v1.x += bv.x; v1.y += bv.y;
                *(float2*)&out[(size_t)m0 * N + n] = v0;
                *(float2*)&out[(size_t)(m0 + 8) * N + n] = v1;
            }
        }
    }
}

// ---------------------------------------------------------------------------
// RoPE in-place on g_q and g_k (only 16 nonzero-frequency pairs per head).
// ---------------------------------------------------------------------------
__global__ void rope_kernel()
{
    const int idx = blockIdx.x * blockDim.x + threadIdx.x;
    const int p = idx & 15;
    const int t = (idx >> 4) & (TT - 1);
    const int bh = idx >> 15;

    const float af = (float)pow(1.0 / 1024.0, (double)p / 15.0);
    const float theta = (float)t * af;
    double sd, cd;
    sincos((double)theta, &sd, &cd);
    const float c = (float)cd, s = (float)sd;

    const size_t base = ((size_t)bh * TT + t) * DD;
    const float q1 = g_q[base + p], q2 = g_q[base + p + 32];
    g_q[base + p]      = q1 * c + q2 * s;
    g_q[base + p + 32] = -q1 * s + q2 * c;
    const float k1 = g_k[base + p], k2 = g_k[base + p + 32];
    g_k[base + p]      = k1 * c + k2 * s;
    g_k[base + p + 32] = -k1 * s + k2 * c;
}

// ---------------------------------------------------------------------------
// Flash attention on HMMA, causal. Br=128 (8 warps x m16), Bc=64.
// Q fragments in registers; K/V hi/lo double-buffered via cp.async.
// S = Qhi Khi + Qhi Klo + Qlo Khi; P split in registers; O += Phi Vhi + ...
// Writes y directly as bf16 hi/lo for the projection GEMM.
// ---------------------------------------------------------------------------
constexpr int RSF = 144;                    // 128B data + 16B pad
constexpr int KVT = 64 * RSF;               // 9216 B per 64x64 bf16 tile
constexpr int KVBUF = 4 * KVT;              // Khi,Klo,Vhi,Vlo = 36864 B
constexpr int FSMEM = 2 * KVBUF;            // 73728 B

__global__ __launch_bounds__(256, 1)
void flash_tc()
{
    extern __shared__ char sp[];
    const uint32_t sb = smem_u32(sp);
    const int qt = 15 - blockIdx.x;         // heavy tiles first
    const int bh = blockIdx.y;
    const int tid = threadIdx.x;
    const int w = tid >> 5;
    const int lane = tid & 31;
    const int g = lane >> 2;
    const int tq = lane & 3;
    const int ntiles = 2 * qt + 2;

    // Stage Q hi/lo into buffer-1 region (reused for kv tile 1 later)
    {
        const size_t qb = ((size_t)bh * TT + (size_t)qt * 128) * DD;
#pragma unroll
        for (int t = 0; t < 8; ++t) {
            const int half = t >> 2;                  // 0: hi, 1: lo
            const int within = (t & 3) * 256 + tid;   // 0..1023
            const int row = within >> 3, c8 = within & 7;
            const __nv_bfloat16* src =
                (half ? g_qlo : g_qhi) + qb + row * 64 + c8 * 8;
            cp16(sb + KVBUF + half * (128 * RSF) + row * RSF + c8 * 16, src);
        }
        cp_commit();
    }

    auto prefetch_kv = [&](int j) {
        const uint32_t dstb = sb + (j & 1) * KVBUF;
        const size_t rb = (size_t)bh * TT + (size_t)j * 64;
#pragma unroll
        for (int t = 0; t < 8; ++t) {
            const int tile = t >> 1;                  // 0..3
            const int within = (t & 1) * 256 + tid;   // 0..511
            const int row = within >> 3, c8 = within & 7;
            const __nv_bfloat16* base =
                (tile == 0) ? g_khi : (tile == 1) ? g_klo
                : (tile == 2) ? g_vhi : g_vlo;
            cp16(dstb + tile * KVT + row * RSF + c8 * 16,
                 base + (rb + row) * 64 + c8 * 8);
        }
        cp_commit();
    };

    prefetch_kv(0);
    cp_wait<1>();          // Q staged
    __syncthreads();

    // Q fragments (4 k-chunks of k16, hi + lo)
    uint32_t qhi[4][4], qlo[4][4];
    {
        const uint32_t qoff =
            (uint32_t)((w * 16 + (lane & 15)) * RSF + ((lane >> 4) * 16));
#pragma unroll
        for (int ks = 0; ks < 4; ++ks) {
            ldsm_x4(qhi[ks], sb + KVBUF + qoff + ks * 32);
            ldsm_x4(qlo[ks], sb + KVBUF + 128 * RSF + qoff + ks * 32);
        }
    }
    __syncthreads();       // Q reads done before kv tile 1 overwrites buf1

    float o[8][4];
#pragma unroll
    for (int i = 0; i < 8; i++)
#pragma unroll
        for (int e = 0; e < 4; e++) o[i][e] = 0.0f;
    float m0 = -1e30f, m1 = -1e30f, l0 = 0.0f, l1 = 0.0f;

    const uint32_t koff = (uint32_t)(((((lane >> 4) << 3) + (lane & 7)) * RSF) +
                                     ((lane >> 3) & 1) * 16);
    const uint32_t voff = (uint32_t)((((((lane >> 3) & 1) << 3) + (lane & 7)) * RSF) +
                                     ((lane >> 4) * 16));
    const int rw = qt * 128 + w * 16;
    const int r0 = rw + g, r1 = rw + g + 8;

    for (int j = 0; j < ntiles; ++j) {
        if (j + 1 < ntiles) { prefetch_kv(j + 1); cp_wait<1>(); }
        else cp_wait<0>();
        __syncthreads();

        const uint32_t bb = sb + (j & 1) * KVBUF;
        const bool skip = (64 * j > rw + 15);    // tile fully above diagonal
        if (!skip) {
            float sc[8][4];
#pragma unroll
            for (int i = 0; i < 8; i++)
#pragma unroll
                for (int e = 0; e < 4; e++) sc[i][e] = 0.0f;

            // S = Q K^T (split, 3 terms)
#pragma unroll
            for (int ks = 0; ks < 4; ++ks) {
#pragma unroll
                for (int ng = 0; ng < 4; ++ng) {
                    uint32_t kh[4], kl[4];
                    const uint32_t a = bb + koff + ng * (16 * RSF) + ks * 32;
                    ldsm_x4(kh, a);
                    ldsm_x4(kl, a + KVT);
                    mma16816(sc[ng * 2],     qhi[ks], kh);
                    mma16816(sc[ng * 2],     qhi[ks], kl);
                    mma16816(sc[ng * 2],     qlo[ks], kh);
                    mma16816(sc[ng * 2 + 1], qhi[ks], kh + 2);
                    mma16816(sc[ng * 2 + 1], qhi[ks], kl + 2);
                    mma16816(sc[ng * 2 + 1], qlo[ks], kh + 2);
                }
            }

            // causal mask (only diagonal-crossing tiles)
            if (64 * j + 63 > rw) {
#pragma unroll
                for (int nt = 0; nt < 8; ++nt) {
                    const int c0 = 64 * j + nt * 8 + 2 * tq;
                    if (c0 > r0)     sc[nt][0] = -1e30f;
                    if (c0 + 1 > r0) sc[nt][1] = -1e30f;
                    if (c0 > r1)     sc[nt][2] = -1e30f;
                    if (c0 + 1 > r1) sc[nt][3] = -1e30f;
                }
            }

            // online softmax (rows g, g+8; quad = lanes sharing g)
            float mx0 = -1e30f, mx1 = -1e30f;
#pragma unroll
            for (int nt = 0; nt < 8; ++nt) {
                mx0 = fmaxf(mx0, fmaxf(sc[nt][0], sc[nt][1]));
                mx1 = fmaxf(mx1, fmaxf(sc[nt][2], sc[nt][3]));
            }
            mx0 = fmaxf(mx0, __shfl_xor_sync(0xffffffffu, mx0, 1));
            mx0 = fmaxf(mx0, __shfl_xor_sync(0xffffffffu, mx0, 2));
            mx1 = fmaxf(mx1, __shfl_xor_sync(0xffffffffu, mx1, 1));
            mx1 = fmaxf(mx1, __shfl_xor_sync(0xffffffffu, mx1, 2));

            const float mn0 = fmaxf(m0, mx0), mn1 = fmaxf(m1, mx1);
            const float a0 = __expf(m0 - mn0), a1 = __expf(m1 - mn1);
            float s0 = 0.0f, s1 = 0.0f;
#pragma unroll
            for (int nt = 0; nt < 8; ++nt) {
                sc[nt][0] = __expf(sc[nt][0] - mn0);
                sc[nt][1] = __expf(sc[nt][1] - mn0);
                sc[nt][2] = __expf(sc[nt][2] - mn1);
                sc[nt][3] = __expf(sc[nt][3] - mn1);
                s0 += sc[nt][0] + sc[nt][1];
                s1 += sc[nt][2] + sc[nt][3];
            }
            s0 += __shfl_xor_sync(0xffffffffu, s0, 1);
            s0 += __shfl_xor_sync(0xffffffffu, s0, 2);
            s1 += __shfl_xor_sync(0xffffffffu, s1, 1);
            s1 += __shfl_xor_sync(0xffffffffu, s1, 2);
            l0 = l0 * a0 + s0;
            l1 = l1 * a1 + s1;
            m0 = mn0; m1 = mn1;
#pragma unroll
            for (int dt = 0; dt < 8; ++dt) {
                o[dt][0] *= a0; o[dt][1] *= a0;
                o[dt][2] *= a1; o[dt][3] *= a1;
            }

            // O += P V (P split in registers, V via ldmatrix.trans)
#pragma unroll
            for (int ks = 0; ks < 4; ++ks) {
                uint32_t phi[4], plo[4];
                pack2(sc[2 * ks][0],     sc[2 * ks][1],     phi[0], plo[0]);
                pack2(sc[2 * ks][2],     sc[2 * ks][3],     phi[1], plo[1]);
                pack2(sc[2 * ks + 1][0], sc[2 * ks + 1][1], phi[2], plo[2]);
                pack2(sc[2 * ks + 1][2], sc[2 * ks + 1][3], phi[3], plo[3]);
#pragma unroll
                for (int dl = 0; dl < 4; ++dl) {
                    uint32_t vh[4], vl[4];
                    const uint32_t a =
                        bb + 2 * KVT + voff + ks * (16 * RSF) + dl * 32;
                    ldsm_x4_t(vh, a);
                    ldsm_x4_t(vl, a + KVT);
                    mma16816(o[dl * 2],     phi, vh);
                    mma16816(o[dl * 2],     phi, vl);
                    mma16816(o[dl * 2],     plo, vh);
                    mma16816(o[dl * 2 + 1], phi, vh + 2);
                    mma16816(o[dl * 2 + 1], phi, vl + 2);
                    mma16816(o[dl * 2 + 1], plo, vh + 2);
                }
            }
        }
        __syncthreads();
    }

    // Epilogue: write y hi/lo directly
    const float inv0 = 1.0f / l0, inv1 = 1.0f / l1;
    const int b = bh >> 4, h = bh & 15;
#pragma unroll
    for (int dt = 0; dt < 8; ++dt) {
        uint32_t hh, ll;
        const size_t i0 = ((size_t)b * TT + r0) * CC + h * 64 + dt * 8 + 2 * tq;
        const size_t i1 = ((size_t)b * TT + r1) * CC + h * 64 + dt * 8 + 2 * tq;
        pack2(o[dt][0] * inv0, o[dt][1] * inv0, hh, ll);
        *(uint32_t*)(g_y_hi + i0) = hh;
        *(uint32_t*)(g_y_lo + i0) = ll;
        pack2(o[dt][2] * inv1, o[dt][3] * inv1, hh, ll);
        *(uint32_t*)(g_y_hi + i1) = hh;
        *(uint32_t*)(g_y_lo + i1) = ll;
    }
}

// ---------------------------------------------------------------------------
// Launch
// ---------------------------------------------------------------------------
extern "C" void kernel_launch(void* const* d_in, const int* in_sizes, int n_in,
                              void* d_out, int out_size)
{
    const float* x        = (const float*)d_in[0];
    const float* qkv_w    = (const float*)d_in[1];
    const float* c_proj_w = (const float*)d_in[2];
    const float* c_proj_b = (const float*)d_in[3];
    float* out = (float*)d_out;

    cudaFuncSetAttribute(gemm_tc<0>,
                         cudaFuncAttributeMaxDynamicSharedMemorySize, GEMM_SMEM);
    cudaFuncSetAttribute(gemm_tc<1>,
                         cudaFuncAttributeMaxDynamicSharedMemorySize, GEMM_SMEM);
    cudaFuncSetAttribute(flash_tc,
                         cudaFuncAttributeMaxDynamicSharedMemorySize, FSMEM);

    // 0. split fp32 -> bf16 hi/lo for x, qkv_w, c_proj_w
    split_k<0><<<(MTOT * CC) / 2048, 256>>>(x);
    split_k<1><<<(NQKV * CC) / 2048, 256>>>(qkv_w);
    split_k<2><<<(CC * CC) / 2048, 256>>>(c_proj_w);

    // 1. QKV projection (HMMA bf16x3): q,k fp32; v directly bf16 hi/lo
    gemm_tc<0><<<dim3(NQKV / 128, MTOT / 128), 256, GEMM_SMEM>>>(
        nullptr, nullptr, NQKV);

    // 2. RoPE in-place on fp32 q,k
    rope_kernel<<<(BB * HH * TT * 16) / 256, 256>>>();

    // 3. q (scaled), k -> bf16 hi/lo
    qk_split<1><<<(BB * HH * TT * DD) / 2048, 256>>>();
    qk_split<0><<<(BB * HH * TT * DD) / 2048, 256>>>();

    // 4. Causal flash attention (HMMA) -> y hi/lo
    flash_tc<<<dim3(TT / 128, BB * HH), 256, FSMEM>>>();

    // 5. Output projection (HMMA bf16x3) + bias -> d_out
    gemm_tc<1><<<dim3(CC / 128, MTOT / 128), 256, GEMM_SMEM>>>(
        c_proj_b, out, CC);
}

// round 16
// speedup vs baseline: 1.0092x; 1.0089x over previous
#include <cuda_runtime.h>
#include <cuda_bf16.h>
#include <math.h>
#include <stdint.h>

// Problem shape (fixed by the reference)
constexpr int BB = 4;
constexpr int TT = 2048;
constexpr int CC = 1024;
constexpr int HH = 16;
constexpr int DD = 64;
constexpr int MTOT = BB * TT;     // 8192
constexpr int NQKV = 3 * CC;      // 3072
constexpr int KDIM = CC;          // 1024

// ---------------------------------------------------------------------------
// Scratch (device globals — no allocation allowed)
// ---------------------------------------------------------------------------
__device__ __align__(16) float g_q[(size_t)BB * HH * TT * DD];   // [B,H,T,D] fp32
__device__ __align__(16) float g_k[(size_t)BB * HH * TT * DD];

// bf16 split-precision copies (hi + lo)
__device__ __align__(16) __nv_bfloat16 g_x_hi[(size_t)MTOT * CC];
__device__ __align__(16) __nv_bfloat16 g_x_lo[(size_t)MTOT * CC];
__device__ __align__(16) __nv_bfloat16 g_w_hi[(size_t)NQKV * CC];
__device__ __align__(16) __nv_bfloat16 g_w_lo[(size_t)NQKV * CC];
__device__ __align__(16) __nv_bfloat16 g_pw_hi[(size_t)CC * CC];
__device__ __align__(16) __nv_bfloat16 g_pw_lo[(size_t)CC * CC];
__device__ __align__(16) __nv_bfloat16 g_y_hi[(size_t)MTOT * CC];
__device__ __align__(16) __nv_bfloat16 g_y_lo[(size_t)MTOT * CC];

// attention operands in bf16 hi/lo, [B,H,T,D]
__device__ __align__(16) __nv_bfloat16 g_qhi[(size_t)BB * HH * TT * DD];
__device__ __align__(16) __nv_bfloat16 g_qlo[(size_t)BB * HH * TT * DD];
__device__ __align__(16) __nv_bfloat16 g_khi[(size_t)BB * HH * TT * DD];
__device__ __align__(16) __nv_bfloat16 g_klo[(size_t)BB * HH * TT * DD];
__device__ __align__(16) __nv_bfloat16 g_vhi[(size_t)BB * HH * TT * DD];
__device__ __align__(16) __nv_bfloat16 g_vlo[(size_t)BB * HH * TT * DD];

// ---------------------------------------------------------------------------
// PTX helpers (compute_103-safe: mma.sync / ldmatrix / cp.async only)
// ---------------------------------------------------------------------------
__device__ __forceinline__ uint32_t smem_u32(const void* p) {
    uint32_t a;
    asm("{ .reg .u64 t; cvta.to.shared.u64 t, %1; cvt.u32.u64 %0, t; }"
        : "=r"(a) : "l"(p));
    return a;
}
__device__ __forceinline__ void cp16(uint32_t dst, const void* src) {
    asm volatile("cp.async.cg.shared.global [%0], [%1], 16;"
                 :: "r"(dst), "l"(src) : "memory");
}
__device__ __forceinline__ void cp_commit() {
    asm volatile("cp.async.commit_group;" ::: "memory");
}
template <int N>
__device__ __forceinline__ void cp_wait() {
    asm volatile("cp.async.wait_group %0;" :: "n"(N) : "memory");
}
__device__ __forceinline__ void ldsm_x4(uint32_t* r, uint32_t addr) {
    asm volatile("ldmatrix.sync.aligned.m8n8.x4.shared.b16 {%0,%1,%2,%3}, [%4];"
                 : "=r"(r[0]), "=r"(r[1]), "=r"(r[2]), "=r"(r[3]) : "r"(addr));
}
__device__ __forceinline__ void ldsm_x4_t(uint32_t* r, uint32_t addr) {
    asm volatile("ldmatrix.sync.aligned.m8n8.x4.trans.shared.b16 {%0,%1,%2,%3}, [%4];"
                 : "=r"(r[0]), "=r"(r[1]), "=r"(r[2]), "=r"(r[3]) : "r"(addr));
}
__device__ __forceinline__ void mma16816(float* c, const uint32_t* a,
                                         const uint32_t* b) {
    asm volatile(
        "mma.sync.aligned.m16n8k16.row.col.f32.bf16.bf16.f32 "
        "{%0,%1,%2,%3}, {%4,%5,%6,%7}, {%8,%9}, {%0,%1,%2,%3};"
        : "+f"(c[0]), "+f"(c[1]), "+f"(c[2]), "+f"(c[3])
        : "r"(a[0]), "r"(a[1]), "r"(a[2]), "r"(a[3]), "r"(b[0]), "r"(b[1]));
}
// Split a float pair into packed bf16 hi and bf16 lo (low half = first elem)
__device__ __forceinline__ void pack2(float a, float b, uint32_t& hi, uint32_t& lo) {
    __nv_bfloat162 h = __floats2bfloat162_rn(a, b);
    __nv_bfloat162 l = __floats2bfloat162_rn(a - __bfloat162float(h.x),
                                             b - __bfloat162float(h.y));
    hi = *(uint32_t*)&h;
    lo = *(uint32_t*)&l;
}

// ---------------------------------------------------------------------------
// Split fp32 -> bf16 hi + bf16 lo.  W selects the (dst hi, dst lo) pair.
// ---------------------------------------------------------------------------
template <int W>
__global__ __launch_bounds__(256) void split_k(const float* __restrict__ s)
{
    __nv_bfloat16 *hi, *lo;
    if (W == 0)      { hi = g_x_hi;  lo = g_x_lo;  }
    else if (W == 1) { hi = g_w_hi;  lo = g_w_lo;  }
    else             { hi = g_pw_hi; lo = g_pw_lo; }

    const size_t base = ((size_t)blockIdx.x * 256 + threadIdx.x) * 8;
    float4 v0 = *(const float4*)(s + base);
    float4 v1 = *(const float4*)(s + base + 4);
    float v[8] = {v0.x, v0.y, v0.z, v0.w, v1.x, v1.y, v1.z, v1.w};
    __align__(16) __nv_bfloat16 h[8];
    __align__(16) __nv_bfloat16 l[8];
#pragma unroll
    for (int i = 0; i < 8; i++) {
        h[i] = __float2bfloat16_rn(v[i]);
        l[i] = __float2bfloat16_rn(v[i] - __bfloat162float(h[i]));
    }
    *(uint4*)(hi + base) = *(const uint4*)h;
    *(uint4*)(lo + base) = *(const uint4*)l;
}

// ---------------------------------------------------------------------------
// Fused RoPE + split: reads fp32 q,k, applies rotation (pairs p,p+32 for
// p<16; identity for p in [16,32)), scales q by 1/8, writes bf16 hi/lo.
// Thread handles elements p, p+16, p+32, p+48 of one (bh,t) row for q and k.
// ---------------------------------------------------------------------------
__global__ __launch_bounds__(256) void rope_split_kernel()
{
    const int idx = blockIdx.x * blockDim.x + threadIdx.x;   // BB*HH*TT*16
    const int p = idx & 15;
    const int t = (idx >> 4) & (TT - 1);
    const int bh = idx >> 15;

    const float af = (float)pow(1.0 / 1024.0, (double)p / 15.0);
    const float theta = (float)t * af;
    double sd, cd;
    sincos((double)theta, &sd, &cd);
    const float c = (float)cd, s = (float)sd;

    const size_t base = ((size_t)bh * TT + t) * DD;

    // q
    {
        const float a0 = g_q[base + p],      a1 = g_q[base + p + 16];
        const float a2 = g_q[base + p + 32], a3 = g_q[base + p + 48];
        float r[4];
        r[0] = (a0 * c + a2 * s) * 0.125f;
        r[2] = (-a0 * s + a2 * c) * 0.125f;
        r[1] = a1 * 0.125f;
        r[3] = a3 * 0.125f;
#pragma unroll
        for (int e = 0; e < 4; e++) {
            const __nv_bfloat16 h = __float2bfloat16_rn(r[e]);
            g_qhi[base + p + e * 16] = h;
            g_qlo[base + p + e * 16] =
                __float2bfloat16_rn(r[e] - __bfloat162float(h));
        }
    }
    // k
    {
        const float a0 = g_k[base + p],      a1 = g_k[base + p + 16];
        const float a2 = g_k[base + p + 32], a3 = g_k[base + p + 48];
        float r[4];
        r[0] = a0 * c + a2 * s;
        r[2] = -a0 * s + a2 * c;
        r[1] = a1;
        r[3] = a3;
#pragma unroll
        for (int e = 0; e < 4; e++) {
            const __nv_bfloat16 h = __float2bfloat16_rn(r[e]);
            g_khi[base + p + e * 16] = h;
            g_klo[base + p + e * 16] =
                __float2bfloat16_rn(r[e] - __bfloat162float(h));
        }
    }
}

// ---------------------------------------------------------------------------
// HMMA bf16x3 GEMM: C[M,N] = A[M,K] * B[N,K]^T in split precision.
// BM=BN=128, BK=32. 8 warps (2x4), each 64x32. Double-buffered cp.async.
// MMAs issued term-major (hh sweep, hl sweep, lh sweep) so same-accumulator
// reuse distance is 16 MMAs -> accumulator RAW latency fully hidden.
// MODE 0: q,k fp32 scatter; v written directly as bf16 hi/lo.
// MODE 1: +bias -> out.
// ---------------------------------------------------------------------------
constexpr int BK = 32;
constexpr int NC = KDIM / BK;              // 32 k-chunks
constexpr int RS = 80;                     // smem row stride (bytes)
constexpr int TILE_B = 128 * RS;           // 10240 B per tile
constexpr int BUF_B = 4 * TILE_B;          // Ah, Al, Bh, Bl = 40960 B
constexpr int GEMM_SMEM = 2 * BUF_B;       // 81920 B

template <int MODE>
__global__ __launch_bounds__(256, 1)
void gemm_tc(const float* __restrict__ bias, float* __restrict__ out, int N)
{
    extern __shared__ char sp[];
    const uint32_t sb = smem_u32(sp);

    const int tid  = threadIdx.x;
    const int wid  = tid >> 5;
    const int lane = tid & 31;
    const int wm   = wid >> 2;
    const int wn   = wid & 3;
    const int tileM = blockIdx.y * 128;
    const int tileN = blockIdx.x * 128;

    const __nv_bfloat16* Ah = (MODE == 0) ? g_x_hi : g_y_hi;
    const __nv_bfloat16* Al = (MODE == 0) ? g_x_lo : g_y_lo;
    const __nv_bfloat16* Bh = (MODE == 0) ? g_w_hi : g_pw_hi;
    const __nv_bfloat16* Bl = (MODE == 0) ? g_w_lo : g_pw_lo;

    const int lrow = tid >> 1;
    const int lcb  = (tid & 1) * 2;
    const size_t gA = (size_t)(tileM + lrow) * KDIM + lcb * 8;
    const size_t gB = (size_t)(tileN + lrow) * KDIM + lcb * 8;
    const uint32_t sOff = (uint32_t)(lrow * RS + lcb * 16);

    auto prefetch = [&](int c) {
        const uint32_t bb = sb + (c & 1) * BUF_B;
        const int k0 = c * BK;
        cp16(bb + sOff,                Ah + gA + k0);
        cp16(bb + sOff + 16,           Ah + gA + k0 + 8);
        cp16(bb + TILE_B + sOff,       Al + gA + k0);
        cp16(bb + TILE_B + sOff + 16,  Al + gA + k0 + 8);
        cp16(bb + 2 * TILE_B + sOff,      Bh + gB + k0);
        cp16(bb + 2 * TILE_B + sOff + 16, Bh + gB + k0 + 8);
        cp16(bb + 3 * TILE_B + sOff,      Bl + gB + k0);
        cp16(bb + 3 * TILE_B + sOff + 16, Bl + gB + k0 + 8);
        cp_commit();
    };

    const uint32_t aoff = (uint32_t)((wm * 64 + (lane & 15)) * RS +
                                     ((lane >> 4) * 16));
    const uint32_t boff = (uint32_t)((wn * 32 + ((lane >> 4) << 3) + (lane & 7)) * RS +
                                     (((lane >> 3) & 1) * 16));

    float acc[4][4][4];
#pragma unroll
    for (int i = 0; i < 4; i++)
#pragma unroll
        for (int j = 0; j < 4; j++)
#pragma unroll
            for (int e = 0; e < 4; e++) acc[i][j][e] = 0.0f;

    prefetch(0);

    for (int c = 0; c < NC; ++c) {
        if (c + 1 < NC) prefetch(c + 1);
        if (c + 1 < NC) cp_wait<1>(); else cp_wait<0>();
        __syncthreads();

        const uint32_t bb = sb + (c & 1) * BUF_B;
#pragma unroll
        for (int ks = 0; ks < 2; ++ks) {
            const uint32_t kb = ks * 32;
            uint32_t ah[4][4], al[4][4], bh[2][4], bl[2][4];
#pragma unroll
            for (int mi = 0; mi < 4; ++mi) {
                ldsm_x4(ah[mi], bb + aoff + mi * (16 * RS) + kb);
                ldsm_x4(al[mi], bb + TILE_B + aoff + mi * (16 * RS) + kb);
            }
#pragma unroll
            for (int n2 = 0; n2 < 2; ++n2) {
                ldsm_x4(bh[n2], bb + 2 * TILE_B + boff + n2 * (16 * RS) + kb);
                ldsm_x4(bl[n2], bb + 3 * TILE_B + boff + n2 * (16 * RS) + kb);
            }
            // term-major: hh sweep, then hl, then lh (acc reuse distance = 16)
#pragma unroll
            for (int mi = 0; mi < 4; ++mi)
#pragma unroll
                for (int ni = 0; ni < 4; ++ni)
                    mma16816(acc[mi][ni], ah[mi], &bh[ni >> 1][(ni & 1) * 2]);
#pragma unroll
            for (int mi = 0; mi < 4; ++mi)
#pragma unroll
                for (int ni = 0; ni < 4; ++ni)
                    mma16816(acc[mi][ni], ah[mi], &bl[ni >> 1][(ni & 1) * 2]);
#pragma unroll
            for (int mi = 0; mi < 4; ++mi)
#pragma unroll
                for (int ni = 0; ni < 4; ++ni)
                    mma16816(acc[mi][ni], al[mi], &bh[ni >> 1][(ni & 1) * 2]);
        }
        __syncthreads();
    }

    const int g4 = lane >> 2;
    const int t4 = lane & 3;
#pragma unroll
    for (int mi = 0; mi < 4; ++mi) {
        const int m0 = tileM + wm * 64 + mi * 16 + g4;
#pragma unroll
        for (int ni = 0; ni < 4; ++ni) {
            const int n = tileN + wn * 32 + ni * 8 + t4 * 2;
            float2 v0 = make_float2(acc[mi][ni][0], acc[mi][ni][1]);
            float2 v1 = make_float2(acc[mi][ni][2], acc[mi][ni][3]);
            if (MODE == 0) {
                const int which = n >> 10;
                const int h = (n & 1023) >> 6;
                const int d = n & 63;
                const int m1 = m0 + 8;
                const size_t i0 =
                    (((size_t)((m0 >> 11) * HH + h)) * TT + (m0 & 2047)) * DD + d;
                const size_t i1 =
                    (((size_t)((m1 >> 11) * HH + h)) * TT + (m1 & 2047)) * DD + d;
                if (which == 2) {
                    uint32_t hh, ll;
                    pack2(v0.x, v0.y, hh, ll);
                    *(uint32_t*)(g_vhi + i0) = hh;
                    *(uint32_t*)(g_vlo + i0) = ll;
                    pack2(v1.x, v1.y, hh, ll);
                    *(uint32_t*)(g_vhi + i1) = hh;
                    *(uint32_t*)(g_vlo + i1) = ll;
                } else {
                    float* dst = (which == 0) ? g_q : g_k;
                    *(float2*)&dst[i0] = v0;
                    *(float2*)&dst[i1] = v1;
                }
            } else {
                const float2 bv = *(const float2*)&bias[n];
                v0.x += bv.x; v0.y += bv.y;
                v1.x += bv.x; v1.y += bv.y;
                *(float2*)&out[(size_t)m0 * N + n] = v0;
                *(float2*)&out[(size_t)(m0 + 8) * N + n] = v1;
            }
        }
    }
}

// ---------------------------------------------------------------------------
// Flash attention on HMMA, causal. Br=128 (8 warps x m16), Bc=64.
// Q fragments in registers; K/V hi/lo double-buffered via cp.async.
// MMAs issued term-major with all fragments preloaded per k-chunk
// (same-accumulator reuse distance = 8).
// Writes y directly as bf16 hi/lo for the projection GEMM.
// ---------------------------------------------------------------------------
constexpr int RSF = 144;                    // 128B data + 16B pad
constexpr int KVT = 64 * RSF;               // 9216 B per 64x64 bf16 tile
constexpr int KVBUF = 4 * KVT;              // Khi,Klo,Vhi,Vlo = 36864 B
constexpr int FSMEM = 2 * KVBUF;            // 73728 B

__global__ __launch_bounds__(256, 1)
void flash_tc()
{
    extern __shared__ char sp[];
    const uint32_t sb = smem_u32(sp);
    const int qt = 15 - blockIdx.x;         // heavy tiles first
    const int bh = blockIdx.y;
    const int tid = threadIdx.x;
    const int w = tid >> 5;
    const int lane = tid & 31;
    const int g = lane >> 2;
    const int tq = lane & 3;
    const int ntiles = 2 * qt + 2;

    // Stage Q hi/lo into buffer-1 region (reused for kv tile 1 later)
    {
        const size_t qb = ((size_t)bh * TT + (size_t)qt * 128) * DD;
#pragma unroll
        for (int t = 0; t < 8; ++t) {
            const int half = t >> 2;                  // 0: hi, 1: lo
            const int within = (t & 3) * 256 + tid;   // 0..1023
            const int row = within >> 3, c8 = within & 7;
            const __nv_bfloat16* src =
                (half ? g_qlo : g_qhi) + qb + row * 64 + c8 * 8;
            cp16(sb + KVBUF + half * (128 * RSF) + row * RSF + c8 * 16, src);
        }
        cp_commit();
    }

    auto prefetch_kv = [&](int j) {
        const uint32_t dstb = sb + (j & 1) * KVBUF;
        const size_t rb = (size_t)bh * TT + (size_t)j * 64;
#pragma unroll
        for (int t = 0; t < 8; ++t) {
            const int tile = t >> 1;                  // 0..3
            const int within = (t & 1) * 256 + tid;   // 0..511
            const int row = within >> 3, c8 = within & 7;
            const __nv_bfloat16* base =
                (tile == 0) ? g_khi : (tile == 1) ? g_klo
                : (tile == 2) ? g_vhi : g_vlo;
            cp16(dstb + tile * KVT + row * RSF + c8 * 16,
                 base + (rb + row) * 64 + c8 * 8);
        }
        cp_commit();
    };

    prefetch_kv(0);
    cp_wait<1>();          // Q staged
    __syncthreads();

    // Q fragments (4 k-chunks of k16, hi + lo)
    uint32_t qhi[4][4], qlo[4][4];
    {
        const uint32_t qoff =
            (uint32_t)((w * 16 + (lane & 15)) * RSF + ((lane >> 4) * 16));
#pragma unroll
        for (int ks = 0; ks < 4; ++ks) {
            ldsm_x4(qhi[ks], sb + KVBUF + qoff + ks * 32);
            ldsm_x4(qlo[ks], sb + KVBUF + 128 * RSF + qoff + ks * 32);
        }
    }
    __syncthreads();       // Q reads done before kv tile 1 overwrites buf1

    float o[8][4];
#pragma unroll
    for (int i = 0; i < 8; i++)
#pragma unroll
        for (int e = 0; e < 4; e++) o[i][e] = 0.0f;
    float m0 = -1e30f, m1 = -1e30f, l0 = 0.0f, l1 = 0.0f;

    const uint32_t koff = (uint32_t)(((((lane >> 4) << 3) + (lane & 7)) * RSF) +
                                     ((lane >> 3) & 1) * 16);
    const uint32_t voff = (uint32_t)((((((lane >> 3) & 1) << 3) + (lane & 7)) * RSF) +
                                     ((lane >> 4) * 16));
    const int rw = qt * 128 + w * 16;
    const int r0 = rw + g, r1 = rw + g + 8;

    for (int j = 0; j < ntiles; ++j) {
        if (j + 1 < ntiles) { prefetch_kv(j + 1); cp_wait<1>(); }
        else cp_wait<0>();
        __syncthreads();

        const uint32_t bb = sb + (j & 1) * KVBUF;
        const bool skip = (64 * j > rw + 15);    // tile fully above diagonal
        if (!skip) {
            float sc[8][4];
#pragma unroll
            for (int i = 0; i < 8; i++)
#pragma unroll
                for (int e = 0; e < 4; e++) sc[i][e] = 0.0f;

            // S = Q K^T (split, 3 terms, term-major per k-chunk)
#pragma unroll
            for (int ks = 0; ks < 4; ++ks) {
                uint32_t kh[4][4], kl[4][4];
#pragma unroll
                for (int ng = 0; ng < 4; ++ng) {
                    const uint32_t a = bb + koff + ng * (16 * RSF) + ks * 32;
                    ldsm_x4(kh[ng], a);
                    ldsm_x4(kl[ng], a + KVT);
                }
#pragma unroll
                for (int ng = 0; ng < 4; ++ng) {
                    mma16816(sc[ng * 2],     qhi[ks], kh[ng]);
                    mma16816(sc[ng * 2 + 1], qhi[ks], kh[ng] + 2);
                }
#pragma unroll
                for (int ng = 0; ng < 4; ++ng) {
                    mma16816(sc[ng * 2],     qhi[ks], kl[ng]);
                    mma16816(sc[ng * 2 + 1], qhi[ks], kl[ng] + 2);
                }
#pragma unroll
                for (int ng = 0; ng < 4; ++ng) {
                    mma16816(sc[ng * 2],     qlo[ks], kh[ng]);
                    mma16816(sc[ng * 2 + 1], qlo[ks], kh[ng] + 2);
                }
            }

            // causal mask (only diagonal-crossing tiles)
            if (64 * j + 63 > rw) {
#pragma unroll
                for (int nt = 0; nt < 8; ++nt) {
                    const int c0 = 64 * j + nt * 8 + 2 * tq;
                    if (c0 > r0)     sc[nt][0] = -1e30f;
                    if (c0 + 1 > r0) sc[nt][1] = -1e30f;
                    if (c0 > r1)     sc[nt][2] = -1e30f;
                    if (c0 + 1 > r1) sc[nt][3] = -1e30f;
                }
            }

            // online softmax (rows g, g+8; quad = lanes sharing g)
            float mx0 = -1e30f, mx1 = -1e30f;
#pragma unroll
            for (int nt = 0; nt < 8; ++nt) {
                mx0 = fmaxf(mx0, fmaxf(sc[nt][0], sc[nt][1]));
                mx1 = fmaxf(mx1, fmaxf(sc[nt][2], sc[nt][3]));
            }
            mx0 = fmaxf(mx0, __shfl_xor_sync(0xffffffffu, mx0, 1));
            mx0 = fmaxf(mx0, __shfl_xor_sync(0xffffffffu, mx0, 2));
            mx1 = fmaxf(mx1, __shfl_xor_sync(0xffffffffu, mx1, 1));
            mx1 = fmaxf(mx1, __shfl_xor_sync(0xffffffffu, mx1, 2));

            const float mn0 = fmaxf(m0, mx0), mn1 = fmaxf(m1, mx1);
            const float a0 = __expf(m0 - mn0), a1 = __expf(m1 - mn1);
            float s0 = 0.0f, s1 = 0.0f;
#pragma unroll
            for (int nt = 0; nt < 8; ++nt) {
                sc[nt][0] = __expf(sc[nt][0] - mn0);
                sc[nt][1] = __expf(sc[nt][1] - mn0);
                sc[nt][2] = __expf(sc[nt][2] - mn1);
                sc[nt][3] = __expf(sc[nt][3] - mn1);
                s0 += sc[nt][0] + sc[nt][1];
                s1 += sc[nt][2] + sc[nt][3];
            }
            s0 += __shfl_xor_sync(0xffffffffu, s0, 1);
            s0 += __shfl_xor_sync(0xffffffffu, s0, 2);
            s1 += __shfl_xor_sync(0xffffffffu, s1, 1);
            s1 += __shfl_xor_sync(0xffffffffu, s1, 2);
            l0 = l0 * a0 + s0;
            l1 = l1 * a1 + s1;
            m0 = mn0; m1 = mn1;
#pragma unroll
            for (int dt = 0; dt < 8; ++dt) {
                o[dt][0] *= a0; o[dt][1] *= a0;
                o[dt][2] *= a1; o[dt][3] *= a1;
            }

            // O += P V (P split in registers, V via ldmatrix.trans;
            // all V fragments preloaded per k-chunk, term-major MMAs)
#pragma unroll
            for (int ks = 0; ks < 4; ++ks) {
                uint32_t phi[4], plo[4];
                pack2(sc[2 * ks][0],     sc[2 * ks][1],     phi[0], plo[0]);
                pack2(sc[2 * ks][2],     sc[2 * ks][3],     phi[1], plo[1]);
                pack2(sc[2 * ks + 1][0], sc[2 * ks + 1][1], phi[2], plo[2]);
                pack2(sc[2 * ks + 1][2], sc[2 * ks + 1][3], phi[3], plo[3]);
                uint32_t vh[4][4], vl[4][4];
#pragma unroll
                for (int dl = 0; dl < 4; ++dl) {
                    const uint32_t a =
                        bb + 2 * KVT + voff + ks * (16 * RSF) + dl * 32;
                    ldsm_x4_t(vh[dl], a);
                    ldsm_x4_t(vl[dl], a + KVT);
                }
#pragma unroll
                for (int dl = 0; dl < 4; ++dl) {
                    mma16816(o[dl * 2],     phi, vh[dl]);
                    mma16816(o[dl * 2 + 1], phi, vh[dl] + 2);
                }
#pragma unroll
                for (int dl = 0; dl < 4; ++dl) {
                    mma16816(o[dl * 2],     phi, vl[dl]);
                    mma16816(o[dl * 2 + 1], phi, vl[dl] + 2);
                }
#pragma unroll
                for (int dl = 0; dl < 4; ++dl) {
                    mma16816(o[dl * 2],     plo, vh[dl]);
                    mma16816(o[dl * 2 + 1], plo, vh[dl] + 2);
                }
            }
        }
        __syncthreads();
    }

    // Epilogue: write y hi/lo directly
    const float inv0 = 1.0f / l0, inv1 = 1.0f / l1;
    const int b = bh >> 4, h = bh & 15;
#pragma unroll
    for (int dt = 0; dt < 8; ++dt) {
        uint32_t hh, ll;
        const size_t i0 = ((size_t)b * TT + r0) * CC + h * 64 + dt * 8 + 2 * tq;
        const size_t i1 = ((size_t)b * TT + r1) * CC + h * 64 + dt * 8 + 2 * tq;
        pack2(o[dt][0] * inv0, o[dt][1] * inv0, hh, ll);
        *(uint32_t*)(g_y_hi + i0) = hh;
        *(uint32_t*)(g_y_lo + i0) = ll;
        pack2(o[dt][2] * inv1, o[dt][3] * inv1, hh, ll);
        *(uint32_t*)(g_y_hi + i1) = hh;
        *(uint32_t*)(g_y_lo + i1) = ll;
    }
}

// ---------------------------------------------------------------------------
// Launch
// ---------------------------------------------------------------------------
extern "C" void kernel_launch(void* const* d_in, const int* in_sizes, int n_in,
                              void* d_out, int out_size)
{
    const float* x        = (const float*)d_in[0];
    const float* qkv_w    = (const float*)d_in[1];
    const float* c_proj_w = (const float*)d_in[2];
    const float* c_proj_b = (const float*)d_in[3];
    float* out = (float*)d_out;

    cudaFuncSetAttribute(gemm_tc<0>,
                         cudaFuncAttributeMaxDynamicSharedMemorySize, GEMM_SMEM);
    cudaFuncSetAttribute(gemm_tc<1>,
                         cudaFuncAttributeMaxDynamicSharedMemorySize, GEMM_SMEM);
    cudaFuncSetAttribute(flash_tc,
                         cudaFuncAttributeMaxDynamicSharedMemorySize, FSMEM);

    // 0. split fp32 -> bf16 hi/lo for x, qkv_w, c_proj_w
    split_k<0><<<(MTOT * CC) / 2048, 256>>>(x);
    split_k<1><<<(NQKV * CC) / 2048, 256>>>(qkv_w);
    split_k<2><<<(CC * CC) / 2048, 256>>>(c_proj_w);

    // 1. QKV projection (HMMA bf16x3): q,k fp32; v directly bf16 hi/lo
    gemm_tc<0><<<dim3(NQKV / 128, MTOT / 128), 256, GEMM_SMEM>>>(
        nullptr, nullptr, NQKV);

    // 2. Fused RoPE + scale + bf16 hi/lo split for q,k
    rope_split_kernel<<<(BB * HH * TT * 16) / 256, 256>>>();

    // 3. Causal flash attention (HMMA) -> y hi/lo
    flash_tc<<<dim3(TT / 128, BB * HH), 256, FSMEM>>>();

    // 4. Output projection (HMMA bf16x3) + bias -> d_out
    gemm_tc<1><<<dim3(CC / 128, MTOT / 128), 256, GEMM_SMEM>>>(
        c_proj_b, out, CC);
}